// round 1
// baseline (speedup 1.0000x reference)
#include <cuda_runtime.h>
#include <cuda_bf16.h>

#define N_EMBD   768
#define N_HEAD   12
#define HEAD_DIM 64
#define BATCH    2
#define SEQ      4096
#define QKV_COLS 2304
#define ROWS     (BATCH * SEQ)   // 8192

// Scratch (device globals: allowed; cudaMalloc is not)
__device__ float g_qkv[(size_t)ROWS * QKV_COLS];  // [8192, 2304]  q|k|v
__device__ float g_y  [(size_t)ROWS * N_EMBD];    // [8192, 768]   attention output

// ---------------------------------------------------------------------------
// Tiled fp32 GEMM:  C[M,N] = A[M,K] @ W[N,K]^T + bias[N]
// BM=BN=64, BK=16, 256 threads, 4x4 per thread.
// ---------------------------------------------------------------------------
__global__ __launch_bounds__(256) void gemm_bias_kernel(
    const float* __restrict__ A, const float* __restrict__ W,
    const float* __restrict__ bias, float* __restrict__ C,
    int M, int N, int K)
{
    __shared__ float As[16][64];
    __shared__ float Ws[16][64];

    const int bm = blockIdx.y * 64;
    const int bn = blockIdx.x * 64;
    const int tid = threadIdx.x;
    const int ty = tid >> 4;          // 0..15  (m direction)
    const int tx = tid & 15;          // 0..15  (n direction)
    const int lr = tid >> 2;          // 0..63  load row
    const int lc = (tid & 3) << 2;    // 0,4,8,12 load col (k)

    float acc[4][4] = {};

    for (int k0 = 0; k0 < K; k0 += 16) {
        float4 a4 = *(const float4*)&A[(size_t)(bm + lr) * K + k0 + lc];
        As[lc + 0][lr] = a4.x; As[lc + 1][lr] = a4.y;
        As[lc + 2][lr] = a4.z; As[lc + 3][lr] = a4.w;
        float4 w4 = *(const float4*)&W[(size_t)(bn + lr) * K + k0 + lc];
        Ws[lc + 0][lr] = w4.x; Ws[lc + 1][lr] = w4.y;
        Ws[lc + 2][lr] = w4.z; Ws[lc + 3][lr] = w4.w;
        __syncthreads();

        #pragma unroll
        for (int kk = 0; kk < 16; kk++) {
            float4 am = *(const float4*)&As[kk][ty << 2];
            float4 wn = *(const float4*)&Ws[kk][tx << 2];
            float amv[4] = {am.x, am.y, am.z, am.w};
            float wnv[4] = {wn.x, wn.y, wn.z, wn.w};
            #pragma unroll
            for (int i = 0; i < 4; i++)
                #pragma unroll
                for (int j = 0; j < 4; j++)
                    acc[i][j] += amv[i] * wnv[j];
        }
        __syncthreads();
    }

    #pragma unroll
    for (int i = 0; i < 4; i++) {
        const int row = bm + (ty << 2) + i;
        #pragma unroll
        for (int j = 0; j < 4; j++) {
            const int col = bn + (tx << 2) + j;
            C[(size_t)row * N + col] = acc[i][j] + bias[col];
        }
    }
}

// ---------------------------------------------------------------------------
// Flash-style attention (fp32).  One block per (b, h, 64-query tile).
// 64 threads; thread t owns query row (qt*64 + t).
// Online softmax over 64-key tiles; Q row and O accumulator in registers.
// ---------------------------------------------------------------------------
__global__ __launch_bounds__(64) void attn_kernel(
    const float* __restrict__ qkv, float* __restrict__ y)
{
    __shared__ float Ks[64][64];   // 16 KB
    __shared__ float Vs[64][64];   // 16 KB
    __shared__ float Ss[64][64];   // 16 KB  Ss[j][q_thread] (conflict-free)

    const int tid = threadIdx.x;      // 0..63 = query within tile
    const int qt  = blockIdx.x;       // 0..63
    const int h   = blockIdx.y;       // 0..11
    const int b   = blockIdx.z;       // 0..1
    const int q   = qt * 64 + tid;
    const float scale = 0.125f;       // 1/sqrt(64)

    // Load this thread's Q row into registers
    const float* qptr = qkv + ((size_t)(b * SEQ + q) * QKV_COLS) + h * HEAD_DIM;
    float qr[HEAD_DIM];
    #pragma unroll
    for (int d = 0; d < HEAD_DIM; d += 4) {
        float4 v = *(const float4*)(qptr + d);
        qr[d] = v.x; qr[d + 1] = v.y; qr[d + 2] = v.z; qr[d + 3] = v.w;
    }

    float m = -1e30f, l = 0.f;
    float O[HEAD_DIM];
    #pragma unroll
    for (int d = 0; d < HEAD_DIM; d++) O[d] = 0.f;

    for (int kt = 0; kt < SEQ / 64; kt++) {
        // Cooperative K/V tile load: thread tid loads key/value row tid
        const float* kp = qkv + ((size_t)(b * SEQ + kt * 64 + tid) * QKV_COLS)
                              + N_EMBD + h * HEAD_DIM;
        const float* vp = kp + N_EMBD;
        #pragma unroll
        for (int d = 0; d < HEAD_DIM; d += 4) {
            *(float4*)&Ks[tid][d] = *(const float4*)(kp + d);
            *(float4*)&Vs[tid][d] = *(const float4*)(vp + d);
        }
        __syncthreads();

        // Pass 1: scores + tile max
        float tmax = -1e30f;
        #pragma unroll 2
        for (int j = 0; j < 64; j++) {
            float s = 0.f;
            #pragma unroll
            for (int d = 0; d < HEAD_DIM; d += 4) {
                float4 kv = *(const float4*)&Ks[j][d];
                s += qr[d] * kv.x + qr[d + 1] * kv.y
                   + qr[d + 2] * kv.z + qr[d + 3] * kv.w;
            }
            s *= scale;
            Ss[j][tid] = s;
            tmax = fmaxf(tmax, s);
        }

        const float mnew  = fmaxf(m, tmax);
        const float alpha = __expf(m - mnew);
        m = mnew;
        l *= alpha;
        #pragma unroll
        for (int d = 0; d < HEAD_DIM; d++) O[d] *= alpha;

        // Pass 2: exp + accumulate P @ V
        #pragma unroll 2
        for (int j = 0; j < 64; j++) {
            const float p = __expf(Ss[j][tid] - mnew);
            l += p;
            #pragma unroll
            for (int d = 0; d < HEAD_DIM; d += 4) {
                float4 vv = *(const float4*)&Vs[j][d];
                O[d]     += p * vv.x;
                O[d + 1] += p * vv.y;
                O[d + 2] += p * vv.z;
                O[d + 3] += p * vv.w;
            }
        }
        __syncthreads();
    }

    const float inv = 1.f / l;
    float* yp = y + ((size_t)(b * SEQ + q) * N_EMBD) + h * HEAD_DIM;
    #pragma unroll
    for (int d = 0; d < HEAD_DIM; d += 4) {
        float4 o;
        o.x = O[d] * inv; o.y = O[d + 1] * inv;
        o.z = O[d + 2] * inv; o.w = O[d + 3] * inv;
        *(float4*)(yp + d) = o;
    }
}

// ---------------------------------------------------------------------------
extern "C" void kernel_launch(void* const* d_in, const int* in_sizes, int n_in,
                              void* d_out, int out_size)
{
    const float* x      = (const float*)d_in[0];
    const float* W_attn = (const float*)d_in[1];
    const float* b_attn = (const float*)d_in[2];
    const float* W_proj = (const float*)d_in[3];
    const float* b_proj = (const float*)d_in[4];
    float* out = (float*)d_out;

    float *qkv, *y;
    cudaGetSymbolAddress((void**)&qkv, g_qkv);
    cudaGetSymbolAddress((void**)&y,   g_y);

    // 1) QKV = x @ W_attn^T + b_attn        [8192, 2304]
    dim3 g1(QKV_COLS / 64, ROWS / 64);
    gemm_bias_kernel<<<g1, 256>>>(x, W_attn, b_attn, qkv, ROWS, QKV_COLS, N_EMBD);

    // 2) attention                           [8192, 768]
    dim3 g2(SEQ / 64, N_HEAD, BATCH);
    attn_kernel<<<g2, 64>>>(qkv, y);

    // 3) out = y @ W_proj^T + b_proj         [8192, 768]
    dim3 g3(N_EMBD / 64, ROWS / 64);
    gemm_bias_kernel<<<g3, 256>>>(y, W_proj, b_proj, out, ROWS, N_EMBD, N_EMBD);
}

// round 3
// speedup vs baseline: 3.4622x; 3.4622x over previous
#include <cuda_runtime.h>
#include <cuda_bf16.h>
#include <cstdint>

#define N_EMBD   768
#define N_HEAD   12
#define HEAD_DIM 64
#define BATCH    2
#define SEQ      4096
#define QKV_COLS 2304
#define ROWS     8192

typedef __nv_bfloat16 bf16;

// ---------------- scratch (device globals; no cudaMalloc allowed) ----------
__device__ bf16 g_xh [(size_t)ROWS * N_EMBD];
__device__ bf16 g_xl [(size_t)ROWS * N_EMBD];
__device__ bf16 g_Wah[(size_t)QKV_COLS * N_EMBD];
__device__ bf16 g_Wal[(size_t)QKV_COLS * N_EMBD];
__device__ bf16 g_Wph[(size_t)N_EMBD * N_EMBD];
__device__ bf16 g_Wpl[(size_t)N_EMBD * N_EMBD];
__device__ bf16 g_qkvh[(size_t)ROWS * QKV_COLS];
__device__ bf16 g_qkvl[(size_t)ROWS * QKV_COLS];
__device__ bf16 g_yh [(size_t)ROWS * N_EMBD];
__device__ bf16 g_yl [(size_t)ROWS * N_EMBD];

// ---------------- helpers --------------------------------------------------
__device__ __forceinline__ void mma16816(float* c, const uint32_t* a,
                                         uint32_t b0, uint32_t b1)
{
    asm volatile(
        "mma.sync.aligned.m16n8k16.row.col.f32.bf16.bf16.f32 "
        "{%0,%1,%2,%3},{%4,%5,%6,%7},{%8,%9},{%0,%1,%2,%3};"
        : "+f"(c[0]), "+f"(c[1]), "+f"(c[2]), "+f"(c[3])
        : "r"(a[0]), "r"(a[1]), "r"(a[2]), "r"(a[3]), "r"(b0), "r"(b1));
}

// split (v0,v1) into packed bf16x2 hi and residual-lo (lo half = v0)
__device__ __forceinline__ void split2(float v0, float v1,
                                       uint32_t& h, uint32_t& l)
{
    __nv_bfloat162 h2 = __floats2bfloat162_rn(v0, v1);
    float2 f = __bfloat1622float2(h2);
    __nv_bfloat162 l2 = __floats2bfloat162_rn(v0 - f.x, v1 - f.y);
    h = *reinterpret_cast<uint32_t*>(&h2);
    l = *reinterpret_cast<uint32_t*>(&l2);
}

__device__ __forceinline__ uint32_t bf2_mul(uint32_t a, uint32_t s)
{
    __nv_bfloat162 av = *reinterpret_cast<__nv_bfloat162*>(&a);
    __nv_bfloat162 sv = *reinterpret_cast<__nv_bfloat162*>(&s);
    __nv_bfloat162 r = __hmul2(av, sv);
    return *reinterpret_cast<uint32_t*>(&r);
}

// ---------------- fp32 -> (bf16 hi, bf16 lo) split -------------------------
__global__ void split_kernel(const float* __restrict__ in,
                             bf16* __restrict__ hi, bf16* __restrict__ lo,
                             int n4)
{
    int i = blockIdx.x * blockDim.x + threadIdx.x;
    if (i >= n4) return;
    float4 v = reinterpret_cast<const float4*>(in)[i];
    __nv_bfloat162 h0 = __floats2bfloat162_rn(v.x, v.y);
    __nv_bfloat162 h1 = __floats2bfloat162_rn(v.z, v.w);
    float2 f0 = __bfloat1622float2(h0);
    float2 f1 = __bfloat1622float2(h1);
    __nv_bfloat162 l0 = __floats2bfloat162_rn(v.x - f0.x, v.y - f0.y);
    __nv_bfloat162 l1 = __floats2bfloat162_rn(v.z - f1.x, v.w - f1.y);
    reinterpret_cast<__nv_bfloat162*>(hi)[2 * i]     = h0;
    reinterpret_cast<__nv_bfloat162*>(hi)[2 * i + 1] = h1;
    reinterpret_cast<__nv_bfloat162*>(lo)[2 * i]     = l0;
    reinterpret_cast<__nv_bfloat162*>(lo)[2 * i + 1] = l1;
}

// ---------------- split-bf16 tensor-core GEMM ------------------------------
// C[M,N] = A[M,K] @ W[N,K]^T + bias, computed as Ah*Wh + Ah*Wl + Al*Wh.
// BM=128, BN=64, BK=32. 128 threads (4 warps), warp tile 32x64 (2 m-tiles).
template<bool SPLIT_OUT>
__global__ __launch_bounds__(128) void gemm_mma(
    const bf16* __restrict__ Ah, const bf16* __restrict__ Al,
    const bf16* __restrict__ Bh, const bf16* __restrict__ Bl,
    const float* __restrict__ bias,
    float* __restrict__ Cf, bf16* __restrict__ Ch, bf16* __restrict__ Cl,
    int M, int N, int K)
{
    __shared__ __align__(16) bf16 sA[2][128][40];   // [hi/lo][m][k(+pad)]
    __shared__ __align__(16) bf16 sB[2][64][40];    // [hi/lo][n][k(+pad)]

    const int tid  = threadIdx.x;
    const int warp = tid >> 5;
    const int lane = tid & 31;
    const int g = lane >> 2;      // 0..7
    const int t = lane & 3;       // 0..3
    const int bm = blockIdx.y * 128;
    const int bn = blockIdx.x * 64;

    float acc[2][8][4] = {};

    for (int k0 = 0; k0 < K; k0 += 32) {
        #pragma unroll
        for (int i = 0; i < 4; i++) {
            int idx = tid + i * 128;
            int row = idx >> 2, seg = idx & 3;
            *(uint4*)&sA[0][row][seg * 8] =
                *(const uint4*)&Ah[(size_t)(bm + row) * K + k0 + seg * 8];
            *(uint4*)&sA[1][row][seg * 8] =
                *(const uint4*)&Al[(size_t)(bm + row) * K + k0 + seg * 8];
        }
        #pragma unroll
        for (int i = 0; i < 2; i++) {
            int idx = tid + i * 128;
            int row = idx >> 2, seg = idx & 3;
            *(uint4*)&sB[0][row][seg * 8] =
                *(const uint4*)&Bh[(size_t)(bn + row) * K + k0 + seg * 8];
            *(uint4*)&sB[1][row][seg * 8] =
                *(const uint4*)&Bl[(size_t)(bn + row) * K + k0 + seg * 8];
        }
        __syncthreads();

        #pragma unroll
        for (int kk = 0; kk < 32; kk += 16) {
            uint32_t a[2][2][4];   // [hi/lo][mtile][frag]
            #pragma unroll
            for (int mt = 0; mt < 2; mt++) {
                int r = warp * 32 + mt * 16;
                #pragma unroll
                for (int p = 0; p < 2; p++) {
                    a[p][mt][0] = *(const uint32_t*)&sA[p][r + g    ][kk + 2 * t];
                    a[p][mt][1] = *(const uint32_t*)&sA[p][r + g + 8][kk + 2 * t];
                    a[p][mt][2] = *(const uint32_t*)&sA[p][r + g    ][kk + 2 * t + 8];
                    a[p][mt][3] = *(const uint32_t*)&sA[p][r + g + 8][kk + 2 * t + 8];
                }
            }
            #pragma unroll
            for (int nt = 0; nt < 8; nt++) {
                uint32_t bh0 = *(const uint32_t*)&sB[0][nt * 8 + g][kk + 2 * t];
                uint32_t bh1 = *(const uint32_t*)&sB[0][nt * 8 + g][kk + 2 * t + 8];
                uint32_t bl0 = *(const uint32_t*)&sB[1][nt * 8 + g][kk + 2 * t];
                uint32_t bl1 = *(const uint32_t*)&sB[1][nt * 8 + g][kk + 2 * t + 8];
                #pragma unroll
                for (int mt = 0; mt < 2; mt++) {
                    mma16816(acc[mt][nt], a[0][mt], bh0, bh1);
                    mma16816(acc[mt][nt], a[0][mt], bl0, bl1);
                    mma16816(acc[mt][nt], a[1][mt], bh0, bh1);
                }
            }
        }
        __syncthreads();
    }

    // epilogue
    #pragma unroll
    for (int mt = 0; mt < 2; mt++) {
        #pragma unroll
        for (int nt = 0; nt < 8; nt++) {
            int row = bm + warp * 32 + mt * 16 + g;
            int col = bn + nt * 8 + 2 * t;
            float2 bs = *(const float2*)&bias[col];
            float v0 = acc[mt][nt][0] + bs.x;
            float v1 = acc[mt][nt][1] + bs.y;
            float v2 = acc[mt][nt][2] + bs.x;
            float v3 = acc[mt][nt][3] + bs.y;
            if (SPLIT_OUT) {
                uint32_t hh, ll;
                split2(v0, v1, hh, ll);
                *(uint32_t*)&Ch[(size_t)row * N + col] = hh;
                *(uint32_t*)&Cl[(size_t)row * N + col] = ll;
                split2(v2, v3, hh, ll);
                *(uint32_t*)&Ch[(size_t)(row + 8) * N + col] = hh;
                *(uint32_t*)&Cl[(size_t)(row + 8) * N + col] = ll;
            } else {
                *(float2*)&Cf[(size_t)row * N + col]       = make_float2(v0, v1);
                *(float2*)&Cf[(size_t)(row + 8) * N + col] = make_float2(v2, v3);
            }
        }
    }
}

// ---------------- flash attention, split-bf16 mma --------------------------
// Block: 256 threads (8 warps), Q tile = 128 rows (16 per warp), one (b,h).
// Loops over 64-key tiles, online softmax, P split to bf16 hi/lo in regs.
__global__ __launch_bounds__(256) void attn_mma(
    const bf16* __restrict__ qh, const bf16* __restrict__ ql,
    bf16* __restrict__ yh, bf16* __restrict__ yl)
{
    __shared__ __align__(16) bf16 sK[2][64][72];   // [hi/lo][key][d(+pad)]
    __shared__ __align__(16) bf16 sV[2][64][72];   // [hi/lo][d][key(+pad)]  (transposed)

    const int tid  = threadIdx.x;
    const int warp = tid >> 5;
    const int lane = tid & 31;
    const int g = lane >> 2;
    const int t = lane & 3;
    const int h = blockIdx.y;
    const int b = blockIdx.z;
    const int qoff  = h * HEAD_DIM;
    const int grow0 = b * SEQ + blockIdx.x * 128 + warp * 16;

    // Q fragments (pre-scaled by 1/sqrt(64) = 0.125, exact in bf16)
    uint32_t qfh[4][4], qfl[4][4];
    const uint32_t sc = 0x3E003E00u;   // bf16x2 {0.125, 0.125}
    #pragma unroll
    for (int kk = 0; kk < 4; kk++) {
        size_t r0 = (size_t)(grow0 + g)     * QKV_COLS + qoff + kk * 16 + 2 * t;
        size_t r1 = (size_t)(grow0 + g + 8) * QKV_COLS + qoff + kk * 16 + 2 * t;
        qfh[kk][0] = bf2_mul(*(const uint32_t*)&qh[r0],     sc);
        qfh[kk][1] = bf2_mul(*(const uint32_t*)&qh[r1],     sc);
        qfh[kk][2] = bf2_mul(*(const uint32_t*)&qh[r0 + 8], sc);
        qfh[kk][3] = bf2_mul(*(const uint32_t*)&qh[r1 + 8], sc);
        qfl[kk][0] = bf2_mul(*(const uint32_t*)&ql[r0],     sc);
        qfl[kk][1] = bf2_mul(*(const uint32_t*)&ql[r1],     sc);
        qfl[kk][2] = bf2_mul(*(const uint32_t*)&ql[r0 + 8], sc);
        qfl[kk][3] = bf2_mul(*(const uint32_t*)&ql[r1 + 8], sc);
    }

    float o[8][4] = {};
    float m0 = -1e30f, m1 = -1e30f, l0 = 0.f, l1 = 0.f;

    for (int kt = 0; kt < SEQ / 64; kt++) {
        const int krow = b * SEQ + kt * 64;
        #pragma unroll
        for (int i = 0; i < 2; i++) {
            int idx = tid + i * 256;
            int row = idx >> 3, seg = idx & 7;
            size_t gcol = (size_t)(krow + row) * QKV_COLS + N_EMBD + qoff + seg * 8;
            *(uint4*)&sK[0][row][seg * 8] = *(const uint4*)&qh[gcol];
            *(uint4*)&sK[1][row][seg * 8] = *(const uint4*)&ql[gcol];
            uint4 vh = *(const uint4*)&qh[gcol + N_EMBD];
            uint4 vl = *(const uint4*)&ql[gcol + N_EMBD];
            const bf16* ph = (const bf16*)&vh;
            const bf16* pl = (const bf16*)&vl;
            #pragma unroll
            for (int j = 0; j < 8; j++) {
                sV[0][seg * 8 + j][row] = ph[j];
                sV[1][seg * 8 + j][row] = pl[j];
            }
        }
        __syncthreads();

        // S = Qs @ K^T  (scaled)
        float s[8][4] = {};
        #pragma unroll
        for (int kk = 0; kk < 4; kk++) {
            #pragma unroll
            for (int nt = 0; nt < 8; nt++) {
                uint32_t bh0 = *(const uint32_t*)&sK[0][nt * 8 + g][kk * 16 + 2 * t];
                uint32_t bh1 = *(const uint32_t*)&sK[0][nt * 8 + g][kk * 16 + 2 * t + 8];
                uint32_t bl0 = *(const uint32_t*)&sK[1][nt * 8 + g][kk * 16 + 2 * t];
                uint32_t bl1 = *(const uint32_t*)&sK[1][nt * 8 + g][kk * 16 + 2 * t + 8];
                mma16816(s[nt], qfh[kk], bh0, bh1);
                mma16816(s[nt], qfh[kk], bl0, bl1);
                mma16816(s[nt], qfl[kk], bh0, bh1);
            }
        }

        // online softmax (rows g and g+8)
        float rmax0 = -1e30f, rmax1 = -1e30f;
        #pragma unroll
        for (int nt = 0; nt < 8; nt++) {
            rmax0 = fmaxf(rmax0, fmaxf(s[nt][0], s[nt][1]));
            rmax1 = fmaxf(rmax1, fmaxf(s[nt][2], s[nt][3]));
        }
        rmax0 = fmaxf(rmax0, __shfl_xor_sync(0xffffffffu, rmax0, 1));
        rmax0 = fmaxf(rmax0, __shfl_xor_sync(0xffffffffu, rmax0, 2));
        rmax1 = fmaxf(rmax1, __shfl_xor_sync(0xffffffffu, rmax1, 1));
        rmax1 = fmaxf(rmax1, __shfl_xor_sync(0xffffffffu, rmax1, 2));

        float mn0 = fmaxf(m0, rmax0), mn1 = fmaxf(m1, rmax1);
        float al0 = __expf(m0 - mn0), al1 = __expf(m1 - mn1);
        m0 = mn0; m1 = mn1;
        #pragma unroll
        for (int nt = 0; nt < 8; nt++) {
            o[nt][0] *= al0; o[nt][1] *= al0;
            o[nt][2] *= al1; o[nt][3] *= al1;
        }

        float ls0 = 0.f, ls1 = 0.f;
        uint32_t ah[4][4], alo[4][4];
        #pragma unroll
        for (int nt = 0; nt < 8; nt++) {
            float p0 = __expf(s[nt][0] - mn0);
            float p1 = __expf(s[nt][1] - mn0);
            float p2 = __expf(s[nt][2] - mn1);
            float p3 = __expf(s[nt][3] - mn1);
            ls0 += p0 + p1;
            ls1 += p2 + p3;
            int kc = nt >> 1, hf = nt & 1;
            split2(p0, p1, ah[kc][hf ? 2 : 0], alo[kc][hf ? 2 : 0]);
            split2(p2, p3, ah[kc][hf ? 3 : 1], alo[kc][hf ? 3 : 1]);
        }
        ls0 += __shfl_xor_sync(0xffffffffu, ls0, 1);
        ls0 += __shfl_xor_sync(0xffffffffu, ls0, 2);
        ls1 += __shfl_xor_sync(0xffffffffu, ls1, 1);
        ls1 += __shfl_xor_sync(0xffffffffu, ls1, 2);
        l0 = l0 * al0 + ls0;
        l1 = l1 * al1 + ls1;

        // O += P @ V
        #pragma unroll
        for (int kc = 0; kc < 4; kc++) {
            #pragma unroll
            for (int nt = 0; nt < 8; nt++) {
                uint32_t bh0 = *(const uint32_t*)&sV[0][nt * 8 + g][kc * 16 + 2 * t];
                uint32_t bh1 = *(const uint32_t*)&sV[0][nt * 8 + g][kc * 16 + 2 * t + 8];
                uint32_t bl0 = *(const uint32_t*)&sV[1][nt * 8 + g][kc * 16 + 2 * t];
                uint32_t bl1 = *(const uint32_t*)&sV[1][nt * 8 + g][kc * 16 + 2 * t + 8];
                mma16816(o[nt], ah[kc], bh0, bh1);
                mma16816(o[nt], ah[kc], bl0, bl1);
                mma16816(o[nt], alo[kc], bh0, bh1);
            }
        }
        __syncthreads();
    }

    // normalize + split + store y (bf16 hi/lo)
    const float inv0 = 1.f / l0, inv1 = 1.f / l1;
    #pragma unroll
    for (int nt = 0; nt < 8; nt++) {
        int col = qoff + nt * 8 + 2 * t;
        size_t r0 = (size_t)(grow0 + g)     * N_EMBD + col;
        size_t r1 = (size_t)(grow0 + g + 8) * N_EMBD + col;
        uint32_t hh, ll;
        split2(o[nt][0] * inv0, o[nt][1] * inv0, hh, ll);
        *(uint32_t*)&yh[r0] = hh;
        *(uint32_t*)&yl[r0] = ll;
        split2(o[nt][2] * inv1, o[nt][3] * inv1, hh, ll);
        *(uint32_t*)&yh[r1] = hh;
        *(uint32_t*)&yl[r1] = ll;
    }
}

// ---------------------------------------------------------------------------
extern "C" void kernel_launch(void* const* d_in, const int* in_sizes, int n_in,
                              void* d_out, int out_size)
{
    const float* x      = (const float*)d_in[0];
    const float* W_attn = (const float*)d_in[1];
    const float* b_attn = (const float*)d_in[2];
    const float* W_proj = (const float*)d_in[3];
    const float* b_proj = (const float*)d_in[4];
    float* out = (float*)d_out;

    bf16 *xh, *xl, *Wah, *Wal, *Wph, *Wpl, *qkvh, *qkvl, *yh, *yl;
    cudaGetSymbolAddress((void**)&xh,  g_xh);
    cudaGetSymbolAddress((void**)&xl,  g_xl);
    cudaGetSymbolAddress((void**)&Wah, g_Wah);
    cudaGetSymbolAddress((void**)&Wal, g_Wal);
    cudaGetSymbolAddress((void**)&Wph, g_Wph);
    cudaGetSymbolAddress((void**)&Wpl, g_Wpl);
    cudaGetSymbolAddress((void**)&qkvh, g_qkvh);
    cudaGetSymbolAddress((void**)&qkvl, g_qkvl);
    cudaGetSymbolAddress((void**)&yh,  g_yh);
    cudaGetSymbolAddress((void**)&yl,  g_yl);

    // split inputs to bf16 hi/lo
    {
        int n4 = ROWS * N_EMBD / 4;
        split_kernel<<<(n4 + 255) / 256, 256>>>(x, xh, xl, n4);
        n4 = QKV_COLS * N_EMBD / 4;
        split_kernel<<<(n4 + 255) / 256, 256>>>(W_attn, Wah, Wal, n4);
        n4 = N_EMBD * N_EMBD / 4;
        split_kernel<<<(n4 + 255) / 256, 256>>>(W_proj, Wph, Wpl, n4);
    }

    // 1) qkv = x @ W_attn^T + b_attn  (epilogue splits to bf16 hi/lo)
    {
        dim3 grid(QKV_COLS / 64, ROWS / 128);
        gemm_mma<true><<<grid, 128>>>(xh, xl, Wah, Wal, b_attn,
                                      nullptr, qkvh, qkvl,
                                      ROWS, QKV_COLS, N_EMBD);
    }

    // 2) flash attention (epilogue splits y to bf16 hi/lo)
    {
        dim3 grid(SEQ / 128, N_HEAD, BATCH);
        attn_mma<<<grid, 256>>>(qkvh, qkvl, yh, yl);
    }

    // 3) out = y @ W_proj^T + b_proj  (fp32 output)
    {
        dim3 grid(N_EMBD / 64, ROWS / 128);
        gemm_mma<false><<<grid, 128>>>(yh, yl, Wph, Wpl, b_proj,
                                       out, nullptr, nullptr,
                                       ROWS, N_EMBD, N_EMBD);
    }
}

// round 5
// speedup vs baseline: 4.7908x; 1.3837x over previous
#include <cuda_runtime.h>
#include <cuda_bf16.h>
#include <cstdint>

#define N_EMBD   768
#define N_HEAD   12
#define HEAD_DIM 64
#define BATCH    2
#define SEQ      4096
#define QKV_COLS 2304
#define ROWS     8192

typedef __nv_bfloat16 bf16;

// ---------------- scratch (device globals; no cudaMalloc allowed) ----------
__device__ bf16 g_xh [(size_t)ROWS * N_EMBD];
__device__ bf16 g_xl [(size_t)ROWS * N_EMBD];
__device__ bf16 g_Wah[(size_t)QKV_COLS * N_EMBD];
__device__ bf16 g_Wal[(size_t)QKV_COLS * N_EMBD];
__device__ bf16 g_Wph[(size_t)N_EMBD * N_EMBD];
__device__ bf16 g_Wpl[(size_t)N_EMBD * N_EMBD];
__device__ bf16 g_qkvh[(size_t)ROWS * QKV_COLS];
__device__ bf16 g_qkvl[(size_t)ROWS * QKV_COLS];
__device__ bf16 g_yh [(size_t)ROWS * N_EMBD];
__device__ bf16 g_yl [(size_t)ROWS * N_EMBD];

// ---------------- low-level helpers ----------------------------------------
__device__ __forceinline__ uint32_t smem_u32(const void* p) {
    return (uint32_t)__cvta_generic_to_shared(p);
}
__device__ __forceinline__ void cp16(const void* s, const void* g) {
    asm volatile("cp.async.cg.shared.global [%0], [%1], 16;"
                 :: "r"(smem_u32(s)), "l"(g));
}
__device__ __forceinline__ void cp_commit() {
    asm volatile("cp.async.commit_group;");
}
template<int N> __device__ __forceinline__ void cp_wait() {
    asm volatile("cp.async.wait_group %0;" :: "n"(N));
}
__device__ __forceinline__ void ldsm4(uint32_t* r, const void* p) {
    asm volatile("ldmatrix.sync.aligned.m8n8.x4.shared.b16 {%0,%1,%2,%3}, [%4];"
                 : "=r"(r[0]), "=r"(r[1]), "=r"(r[2]), "=r"(r[3])
                 : "r"(smem_u32(p)));
}
__device__ __forceinline__ void ldsm4t(uint32_t* r, const void* p) {
    asm volatile("ldmatrix.sync.aligned.m8n8.x4.trans.shared.b16 {%0,%1,%2,%3}, [%4];"
                 : "=r"(r[0]), "=r"(r[1]), "=r"(r[2]), "=r"(r[3])
                 : "r"(smem_u32(p)));
}
__device__ __forceinline__ void mma16816(float* c, const uint32_t* a,
                                         uint32_t b0, uint32_t b1)
{
    asm volatile(
        "mma.sync.aligned.m16n8k16.row.col.f32.bf16.bf16.f32 "
        "{%0,%1,%2,%3},{%4,%5,%6,%7},{%8,%9},{%0,%1,%2,%3};"
        : "+f"(c[0]), "+f"(c[1]), "+f"(c[2]), "+f"(c[3])
        : "r"(a[0]), "r"(a[1]), "r"(a[2]), "r"(a[3]), "r"(b0), "r"(b1));
}
__device__ __forceinline__ void split2(float v0, float v1,
                                       uint32_t& h, uint32_t& l)
{
    __nv_bfloat162 h2 = __floats2bfloat162_rn(v0, v1);
    float2 f = __bfloat1622float2(h2);
    __nv_bfloat162 l2 = __floats2bfloat162_rn(v0 - f.x, v1 - f.y);
    h = *reinterpret_cast<uint32_t*>(&h2);
    l = *reinterpret_cast<uint32_t*>(&l2);
}
__device__ __forceinline__ uint32_t bf2_mul(uint32_t a, uint32_t s)
{
    __nv_bfloat162 av = *reinterpret_cast<__nv_bfloat162*>(&a);
    __nv_bfloat162 sv = *reinterpret_cast<__nv_bfloat162*>(&s);
    __nv_bfloat162 r = __hmul2(av, sv);
    return *reinterpret_cast<uint32_t*>(&r);
}

// ---------------- fp32 -> (bf16 hi, bf16 lo) split -------------------------
__global__ void split_kernel(const float* __restrict__ in,
                             bf16* __restrict__ hi, bf16* __restrict__ lo,
                             int n4)
{
    int i = blockIdx.x * blockDim.x + threadIdx.x;
    if (i >= n4) return;
    float4 v = reinterpret_cast<const float4*>(in)[i];
    __nv_bfloat162 h0 = __floats2bfloat162_rn(v.x, v.y);
    __nv_bfloat162 h1 = __floats2bfloat162_rn(v.z, v.w);
    float2 f0 = __bfloat1622float2(h0);
    float2 f1 = __bfloat1622float2(h1);
    __nv_bfloat162 l0 = __floats2bfloat162_rn(v.x - f0.x, v.y - f0.y);
    __nv_bfloat162 l1 = __floats2bfloat162_rn(v.z - f1.x, v.w - f1.y);
    reinterpret_cast<__nv_bfloat162*>(hi)[2 * i]     = h0;
    reinterpret_cast<__nv_bfloat162*>(hi)[2 * i + 1] = h1;
    reinterpret_cast<__nv_bfloat162*>(lo)[2 * i]     = l0;
    reinterpret_cast<__nv_bfloat162*>(lo)[2 * i + 1] = l1;
}

// ---------------- split-bf16 GEMM, cp.async double-buffered ---------------
// C[M,N] = A[M,K] @ W[N,K]^T + bias;  Ah*Wh + Ah*Wl + Al*Wh.
// 256 threads (8 warps 4x2), BM=128, BN=128, BK=32; warp tile 32x64.
// dyn smem: sA[2][2][128][40], sB[2][2][128][40]  (80 KB)
#define GA(buf,p,r,c) (smp      + (((buf)*2 + (p)) * 128 + (r)) * 40 + (c))
#define GB(buf,p,r,c) (smp + 20480 + (((buf)*2 + (p)) * 128 + (r)) * 40 + (c))

template<bool SPLIT_OUT>
__global__ __launch_bounds__(256) void gemm_mma(
    const bf16* __restrict__ Ah, const bf16* __restrict__ Al,
    const bf16* __restrict__ Bh, const bf16* __restrict__ Bl,
    const float* __restrict__ bias,
    float* __restrict__ Cf, bf16* __restrict__ Ch, bf16* __restrict__ Cl,
    int M, int N, int K)
{
    extern __shared__ __align__(16) bf16 smp[];

    const int tid  = threadIdx.x;
    const int warp = tid >> 5;
    const int lane = tid & 31;
    const int g = lane >> 2;
    const int t = lane & 3;
    const int wm = (warp >> 1) * 32;      // warp m offset within block
    const int wn = (warp & 1) * 64;       // warp n offset within block
    const int bm = blockIdx.y * 128;
    const int bn = blockIdx.x * 128;

    const int crow = tid >> 1;            // 0..127
    const int ccol = (tid & 1) * 16;      // 0 or 16 (elems)

    // ldmatrix lane -> (row, col) offsets
    const int lq = lane >> 3, lr = lane & 7;
    const int a_ro = (lq & 1) * 8, a_co = (lq >> 1) * 8;   // A frag (a0,a1,a2,a3)
    const int b_ro = (lq >> 1) * 8, b_co = (lq & 1) * 8;   // B frag (b0,b1,nb0,nb1)

    float acc[2][8][4] = {};
    const int iters = K / 32;

    // prologue: load tile 0
    {
        const bf16* a0 = Ah + (size_t)(bm + crow) * K + ccol;
        const bf16* a1 = Al + (size_t)(bm + crow) * K + ccol;
        const bf16* b0 = Bh + (size_t)(bn + crow) * K + ccol;
        const bf16* b1 = Bl + (size_t)(bn + crow) * K + ccol;
        cp16(GA(0,0,crow,ccol), a0);   cp16(GA(0,0,crow,ccol+8), a0+8);
        cp16(GA(0,1,crow,ccol), a1);   cp16(GA(0,1,crow,ccol+8), a1+8);
        cp16(GB(0,0,crow,ccol), b0);   cp16(GB(0,0,crow,ccol+8), b0+8);
        cp16(GB(0,1,crow,ccol), b1);   cp16(GB(0,1,crow,ccol+8), b1+8);
        cp_commit();
    }

    for (int it = 0; it < iters; it++) {
        if (it + 1 < iters) {
            const int k0 = (it + 1) * 32;
            const int nb = (it + 1) & 1;
            const bf16* a0 = Ah + (size_t)(bm + crow) * K + k0 + ccol;
            const bf16* a1 = Al + (size_t)(bm + crow) * K + k0 + ccol;
            const bf16* b0 = Bh + (size_t)(bn + crow) * K + k0 + ccol;
            const bf16* b1 = Bl + (size_t)(bn + crow) * K + k0 + ccol;
            cp16(GA(nb,0,crow,ccol), a0);   cp16(GA(nb,0,crow,ccol+8), a0+8);
            cp16(GA(nb,1,crow,ccol), a1);   cp16(GA(nb,1,crow,ccol+8), a1+8);
            cp16(GB(nb,0,crow,ccol), b0);   cp16(GB(nb,0,crow,ccol+8), b0+8);
            cp16(GB(nb,1,crow,ccol), b1);   cp16(GB(nb,1,crow,ccol+8), b1+8);
            cp_commit();
            cp_wait<1>();
        } else {
            cp_wait<0>();
        }
        __syncthreads();

        const int buf = it & 1;
        #pragma unroll
        for (int kk = 0; kk < 32; kk += 16) {
            uint32_t a[2][2][4];            // [p][mt][frag]
            #pragma unroll
            for (int mt = 0; mt < 2; mt++) {
                ldsm4(a[0][mt], GA(buf,0, wm + mt*16 + a_ro + lr, kk + a_co));
                ldsm4(a[1][mt], GA(buf,1, wm + mt*16 + a_ro + lr, kk + a_co));
            }
            #pragma unroll
            for (int ntp = 0; ntp < 4; ntp++) {
                uint32_t rh[4], rl[4];
                ldsm4(rh, GB(buf,0, wn + ntp*16 + b_ro + lr, kk + b_co));
                ldsm4(rl, GB(buf,1, wn + ntp*16 + b_ro + lr, kk + b_co));
                #pragma unroll
                for (int hv = 0; hv < 2; hv++) {
                    const int nt = 2*ntp + hv;
                    const uint32_t bh0 = rh[2*hv], bh1 = rh[2*hv+1];
                    const uint32_t bl0 = rl[2*hv], bl1 = rl[2*hv+1];
                    #pragma unroll
                    for (int mt = 0; mt < 2; mt++) {
                        mma16816(acc[mt][nt], a[0][mt], bh0, bh1);
                        mma16816(acc[mt][nt], a[0][mt], bl0, bl1);
                        mma16816(acc[mt][nt], a[1][mt], bh0, bh1);
                    }
                }
            }
        }
        __syncthreads();
    }

    // epilogue
    #pragma unroll
    for (int mt = 0; mt < 2; mt++) {
        #pragma unroll
        for (int nt = 0; nt < 8; nt++) {
            const int row = bm + wm + mt*16 + g;
            const int col = bn + wn + nt*8 + 2*t;
            float2 bs = *(const float2*)&bias[col];
            float v0 = acc[mt][nt][0] + bs.x;
            float v1 = acc[mt][nt][1] + bs.y;
            float v2 = acc[mt][nt][2] + bs.x;
            float v3 = acc[mt][nt][3] + bs.y;
            if (SPLIT_OUT) {
                uint32_t hh, ll;
                split2(v0, v1, hh, ll);
                *(uint32_t*)&Ch[(size_t)row * N + col] = hh;
                *(uint32_t*)&Cl[(size_t)row * N + col] = ll;
                split2(v2, v3, hh, ll);
                *(uint32_t*)&Ch[(size_t)(row + 8) * N + col] = hh;
                *(uint32_t*)&Cl[(size_t)(row + 8) * N + col] = ll;
            } else {
                *(float2*)&Cf[(size_t)row * N + col]       = make_float2(v0, v1);
                *(float2*)&Cf[(size_t)(row + 8) * N + col] = make_float2(v2, v3);
            }
        }
    }
}

// ---------------- flash attention, cp.async + ldmatrix ---------------------
// 256 threads (8 warps), Q tile 128 (16 rows/warp), key tile 64.
// dyn smem: K[2][2][64][72] then V[2][2][64][72]  (72 KB). V kept row-major;
// P@V B-fragments come from ldmatrix.x4.trans.
#define AK(buf,p,r,c) (smp + ((((buf)*2 + (p))    ) * 64 + (r)) * 72 + (c))
#define AV(buf,p,r,c) (smp + ((((buf)*2 + (p)) + 4) * 64 + (r)) * 72 + (c))

__global__ __launch_bounds__(256) void attn_mma(
    const bf16* __restrict__ qh, const bf16* __restrict__ ql,
    bf16* __restrict__ yh, bf16* __restrict__ yl)
{
    extern __shared__ __align__(16) bf16 smp[];

    const int tid  = threadIdx.x;
    const int warp = tid >> 5;
    const int lane = tid & 31;
    const int g = lane >> 2;
    const int t = lane & 3;
    const int h = blockIdx.y;
    const int b = blockIdx.z;
    const int qoff  = h * HEAD_DIM;
    const int grow0 = b * SEQ + blockIdx.x * 128 + warp * 16;

    const int crow = tid >> 2;            // 0..63
    const int cseg = (tid & 3) * 16;      // 0,16,32,48 (elems)

    const int lq = lane >> 3, lr = lane & 7;
    const int k_ro = (lq >> 1) * 8, k_co = (lq & 1) * 8;   // QK B (non-trans)
    const int v_ro = (lq & 1) * 8,  v_co = (lq >> 1) * 8;  // PV B (trans)

    // Q fragments, pre-scaled by 0.125 (exact in bf16)
    uint32_t qfh[4][4], qfl[4][4];
    const uint32_t sc = 0x3E003E00u;
    #pragma unroll
    for (int kk = 0; kk < 4; kk++) {
        size_t r0 = (size_t)(grow0 + g)     * QKV_COLS + qoff + kk * 16 + 2 * t;
        size_t r1 = (size_t)(grow0 + g + 8) * QKV_COLS + qoff + kk * 16 + 2 * t;
        qfh[kk][0] = bf2_mul(*(const uint32_t*)&qh[r0],     sc);
        qfh[kk][1] = bf2_mul(*(const uint32_t*)&qh[r1],     sc);
        qfh[kk][2] = bf2_mul(*(const uint32_t*)&qh[r0 + 8], sc);
        qfh[kk][3] = bf2_mul(*(const uint32_t*)&qh[r1 + 8], sc);
        qfl[kk][0] = bf2_mul(*(const uint32_t*)&ql[r0],     sc);
        qfl[kk][1] = bf2_mul(*(const uint32_t*)&ql[r1],     sc);
        qfl[kk][2] = bf2_mul(*(const uint32_t*)&ql[r0 + 8], sc);
        qfl[kk][3] = bf2_mul(*(const uint32_t*)&ql[r1 + 8], sc);
    }

    float o[8][4] = {};
    float m0 = -1e30f, m1 = -1e30f, l0 = 0.f, l1 = 0.f;

    // tile loader
    auto load_tile = [&](int kt, int buf) {
        const size_t base = (size_t)(b * SEQ + kt * 64 + crow) * QKV_COLS
                          + qoff + cseg;
        const bf16* skh = qh + base + N_EMBD;
        const bf16* skl = ql + base + N_EMBD;
        const bf16* svh = qh + base + 2 * N_EMBD;
        const bf16* svl = ql + base + 2 * N_EMBD;
        cp16(AK(buf,0,crow,cseg), skh);  cp16(AK(buf,0,crow,cseg+8), skh+8);
        cp16(AK(buf,1,crow,cseg), skl);  cp16(AK(buf,1,crow,cseg+8), skl+8);
        cp16(AV(buf,0,crow,cseg), svh);  cp16(AV(buf,0,crow,cseg+8), svh+8);
        cp16(AV(buf,1,crow,cseg), svl);  cp16(AV(buf,1,crow,cseg+8), svl+8);
        cp_commit();
    };

    load_tile(0, 0);

    const int NT = SEQ / 64;
    for (int kt = 0; kt < NT; kt++) {
        if (kt + 1 < NT) { load_tile(kt + 1, (kt + 1) & 1); cp_wait<1>(); }
        else             { cp_wait<0>(); }
        __syncthreads();
        const int buf = kt & 1;

        // ---- S = Qs @ K^T ----
        float s[8][4] = {};
        #pragma unroll
        for (int kk = 0; kk < 4; kk++) {
            #pragma unroll
            for (int ntp = 0; ntp < 4; ntp++) {
                uint32_t rh[4], rl[4];
                ldsm4(rh, AK(buf,0, ntp*16 + k_ro + lr, kk*16 + k_co));
                ldsm4(rl, AK(buf,1, ntp*16 + k_ro + lr, kk*16 + k_co));
                #pragma unroll
                for (int hv = 0; hv < 2; hv++) {
                    const int nt = 2*ntp + hv;
                    mma16816(s[nt], qfh[kk], rh[2*hv], rh[2*hv+1]);
                    mma16816(s[nt], qfh[kk], rl[2*hv], rl[2*hv+1]);
                    mma16816(s[nt], qfl[kk], rh[2*hv], rh[2*hv+1]);
                }
            }
        }

        // ---- online softmax ----
        float rmax0 = -1e30f, rmax1 = -1e30f;
        #pragma unroll
        for (int nt = 0; nt < 8; nt++) {
            rmax0 = fmaxf(rmax0, fmaxf(s[nt][0], s[nt][1]));
            rmax1 = fmaxf(rmax1, fmaxf(s[nt][2], s[nt][3]));
        }
        rmax0 = fmaxf(rmax0, __shfl_xor_sync(0xffffffffu, rmax0, 1));
        rmax0 = fmaxf(rmax0, __shfl_xor_sync(0xffffffffu, rmax0, 2));
        rmax1 = fmaxf(rmax1, __shfl_xor_sync(0xffffffffu, rmax1, 1));
        rmax1 = fmaxf(rmax1, __shfl_xor_sync(0xffffffffu, rmax1, 2));

        float mn0 = fmaxf(m0, rmax0), mn1 = fmaxf(m1, rmax1);
        float al0 = __expf(m0 - mn0), al1 = __expf(m1 - mn1);
        m0 = mn0; m1 = mn1;
        #pragma unroll
        for (int nt = 0; nt < 8; nt++) {
            o[nt][0] *= al0; o[nt][1] *= al0;
            o[nt][2] *= al1; o[nt][3] *= al1;
        }

        float ls0 = 0.f, ls1 = 0.f;
        uint32_t ah[4][4], alo[4][4];
        #pragma unroll
        for (int nt = 0; nt < 8; nt++) {
            float p0 = __expf(s[nt][0] - mn0);
            float p1 = __expf(s[nt][1] - mn0);
            float p2 = __expf(s[nt][2] - mn1);
            float p3 = __expf(s[nt][3] - mn1);
            ls0 += p0 + p1;
            ls1 += p2 + p3;
            const int kc = nt >> 1, hf = nt & 1;
            split2(p0, p1, ah[kc][hf ? 2 : 0], alo[kc][hf ? 2 : 0]);
            split2(p2, p3, ah[kc][hf ? 3 : 1], alo[kc][hf ? 3 : 1]);
        }
        ls0 += __shfl_xor_sync(0xffffffffu, ls0, 1);
        ls0 += __shfl_xor_sync(0xffffffffu, ls0, 2);
        ls1 += __shfl_xor_sync(0xffffffffu, ls1, 1);
        ls1 += __shfl_xor_sync(0xffffffffu, ls1, 2);
        l0 = l0 * al0 + ls0;
        l1 = l1 * al1 + ls1;

        // ---- O += P @ V  (B frags via ldmatrix.trans from row-major V) ----
        #pragma unroll
        for (int kc = 0; kc < 4; kc++) {
            #pragma unroll
            for (int dtp = 0; dtp < 4; dtp++) {
                uint32_t rh[4], rl[4];
                ldsm4t(rh, AV(buf,0, kc*16 + v_ro + lr, dtp*16 + v_co));
                ldsm4t(rl, AV(buf,1, kc*16 + v_ro + lr, dtp*16 + v_co));
                #pragma unroll
                for (int hv = 0; hv < 2; hv++) {
                    const int nt = 2*dtp + hv;
                    mma16816(o[nt], ah[kc],  rh[2*hv], rh[2*hv+1]);
                    mma16816(o[nt], ah[kc],  rl[2*hv], rl[2*hv+1]);
                    mma16816(o[nt], alo[kc], rh[2*hv], rh[2*hv+1]);
                }
            }
        }
        __syncthreads();
    }

    // normalize + split + store
    const float inv0 = 1.f / l0, inv1 = 1.f / l1;
    #pragma unroll
    for (int nt = 0; nt < 8; nt++) {
        const int col = qoff + nt * 8 + 2 * t;
        size_t r0 = (size_t)(grow0 + g)     * N_EMBD + col;
        size_t r1 = (size_t)(grow0 + g + 8) * N_EMBD + col;
        uint32_t hh, ll;
        split2(o[nt][0] * inv0, o[nt][1] * inv0, hh, ll);
        *(uint32_t*)&yh[r0] = hh;
        *(uint32_t*)&yl[r0] = ll;
        split2(o[nt][2] * inv1, o[nt][3] * inv1, hh, ll);
        *(uint32_t*)&yh[r1] = hh;
        *(uint32_t*)&yl[r1] = ll;
    }
}

// ---------------------------------------------------------------------------
extern "C" void kernel_launch(void* const* d_in, const int* in_sizes, int n_in,
                              void* d_out, int out_size)
{
    const float* x      = (const float*)d_in[0];
    const float* W_attn = (const float*)d_in[1];
    const float* b_attn = (const float*)d_in[2];
    const float* W_proj = (const float*)d_in[3];
    const float* b_proj = (const float*)d_in[4];
    float* out = (float*)d_out;

    bf16 *xh, *xl, *Wah, *Wal, *Wph, *Wpl, *qkvh, *qkvl, *yh, *yl;
    cudaGetSymbolAddress((void**)&xh,  g_xh);
    cudaGetSymbolAddress((void**)&xl,  g_xl);
    cudaGetSymbolAddress((void**)&Wah, g_Wah);
    cudaGetSymbolAddress((void**)&Wal, g_Wal);
    cudaGetSymbolAddress((void**)&Wph, g_Wph);
    cudaGetSymbolAddress((void**)&Wpl, g_Wpl);
    cudaGetSymbolAddress((void**)&qkvh, g_qkvh);
    cudaGetSymbolAddress((void**)&qkvl, g_qkvl);
    cudaGetSymbolAddress((void**)&yh,  g_yh);
    cudaGetSymbolAddress((void**)&yl,  g_yl);

    const int GEMM_SMEM = 2 * 2 * 128 * 40 * 2 * (int)sizeof(bf16); // 81920
    const int ATTN_SMEM = 8 * 64 * 72 * (int)sizeof(bf16);          // 73728
    cudaFuncSetAttribute(gemm_mma<true>,
        cudaFuncAttributeMaxDynamicSharedMemorySize, GEMM_SMEM);
    cudaFuncSetAttribute(gemm_mma<false>,
        cudaFuncAttributeMaxDynamicSharedMemorySize, GEMM_SMEM);
    cudaFuncSetAttribute(attn_mma,
        cudaFuncAttributeMaxDynamicSharedMemorySize, ATTN_SMEM);

    // split inputs to bf16 hi/lo
    {
        int n4 = ROWS * N_EMBD / 4;
        split_kernel<<<(n4 + 255) / 256, 256>>>(x, xh, xl, n4);
        n4 = QKV_COLS * N_EMBD / 4;
        split_kernel<<<(n4 + 255) / 256, 256>>>(W_attn, Wah, Wal, n4);
        n4 = N_EMBD * N_EMBD / 4;
        split_kernel<<<(n4 + 255) / 256, 256>>>(W_proj, Wph, Wpl, n4);
    }

    // 1) qkv = x @ W_attn^T + b_attn  (epilogue splits to bf16 hi/lo)
    {
        dim3 grid(QKV_COLS / 128, ROWS / 128);
        gemm_mma<true><<<grid, 256, GEMM_SMEM>>>(xh, xl, Wah, Wal, b_attn,
                                                 nullptr, qkvh, qkvl,
                                                 ROWS, QKV_COLS, N_EMBD);
    }

    // 2) flash attention
    {
        dim3 grid(SEQ / 128, N_HEAD, BATCH);
        attn_mma<<<grid, 256, ATTN_SMEM>>>(qkvh, qkvl, yh, yl);
    }

    // 3) out = y @ W_proj^T + b_proj  (fp32 output)
    {
        dim3 grid(N_EMBD / 128, ROWS / 128);
        gemm_mma<false><<<grid, 256, GEMM_SMEM>>>(yh, yl, Wph, Wpl, b_proj,
                                                  out, nullptr, nullptr,
                                                  ROWS, N_EMBD, N_EMBD);
    }
}

// round 9
// speedup vs baseline: 5.2284x; 1.0913x over previous
#include <cuda_runtime.h>
#include <cuda_bf16.h>
#include <cstdint>

#define N_EMBD   768
#define N_HEAD   12
#define HEAD_DIM 64
#define BATCH    2
#define SEQ      4096
#define QKV_COLS 2304
#define ROWS     8192

typedef __nv_bfloat16 bf16;

// ---------------- scratch (device globals; no cudaMalloc allowed) ----------
__device__ bf16 g_xh [(size_t)ROWS * N_EMBD];
__device__ bf16 g_xl [(size_t)ROWS * N_EMBD];
__device__ bf16 g_Wah[(size_t)QKV_COLS * N_EMBD];
__device__ bf16 g_Wal[(size_t)QKV_COLS * N_EMBD];
__device__ bf16 g_Wph[(size_t)N_EMBD * N_EMBD];
__device__ bf16 g_Wpl[(size_t)N_EMBD * N_EMBD];
__device__ bf16 g_qkvh[(size_t)ROWS * QKV_COLS];
__device__ bf16 g_qkvl[(size_t)ROWS * QKV_COLS];
__device__ bf16 g_yh [(size_t)ROWS * N_EMBD];
__device__ bf16 g_yl [(size_t)ROWS * N_EMBD];

// ---------------- low-level helpers ----------------------------------------
__device__ __forceinline__ uint32_t smem_u32(const void* p) {
    return (uint32_t)__cvta_generic_to_shared(p);
}
__device__ __forceinline__ void cp16(const void* s, const void* g) {
    asm volatile("cp.async.cg.shared.global [%0], [%1], 16;"
                 :: "r"(smem_u32(s)), "l"(g));
}
__device__ __forceinline__ void cp_commit() {
    asm volatile("cp.async.commit_group;");
}
template<int N> __device__ __forceinline__ void cp_wait() {
    asm volatile("cp.async.wait_group %0;" :: "n"(N));
}
__device__ __forceinline__ void ldsm4(uint32_t* r, const void* p) {
    asm volatile("ldmatrix.sync.aligned.m8n8.x4.shared.b16 {%0,%1,%2,%3}, [%4];"
                 : "=r"(r[0]), "=r"(r[1]), "=r"(r[2]), "=r"(r[3])
                 : "r"(smem_u32(p)));
}
__device__ __forceinline__ void ldsm4t(uint32_t* r, const void* p) {
    asm volatile("ldmatrix.sync.aligned.m8n8.x4.trans.shared.b16 {%0,%1,%2,%3}, [%4];"
                 : "=r"(r[0]), "=r"(r[1]), "=r"(r[2]), "=r"(r[3])
                 : "r"(smem_u32(p)));
}
__device__ __forceinline__ void mma16816(float* c, const uint32_t* a,
                                         uint32_t b0, uint32_t b1)
{
    asm volatile(
        "mma.sync.aligned.m16n8k16.row.col.f32.bf16.bf16.f32 "
        "{%0,%1,%2,%3},{%4,%5,%6,%7},{%8,%9},{%0,%1,%2,%3};"
        : "+f"(c[0]), "+f"(c[1]), "+f"(c[2]), "+f"(c[3])
        : "r"(a[0]), "r"(a[1]), "r"(a[2]), "r"(a[3]), "r"(b0), "r"(b1));
}
__device__ __forceinline__ void split2(float v0, float v1,
                                       uint32_t& h, uint32_t& l)
{
    __nv_bfloat162 h2 = __floats2bfloat162_rn(v0, v1);
    float2 f = __bfloat1622float2(h2);
    __nv_bfloat162 l2 = __floats2bfloat162_rn(v0 - f.x, v1 - f.y);
    h = *reinterpret_cast<uint32_t*>(&h2);
    l = *reinterpret_cast<uint32_t*>(&l2);
}
__device__ __forceinline__ uint32_t bf2_mul(uint32_t a, uint32_t s)
{
    __nv_bfloat162 av = *reinterpret_cast<__nv_bfloat162*>(&a);
    __nv_bfloat162 sv = *reinterpret_cast<__nv_bfloat162*>(&s);
    __nv_bfloat162 r = __hmul2(av, sv);
    return *reinterpret_cast<uint32_t*>(&r);
}

// ---------------- fp32 -> (bf16 hi, bf16 lo) split -------------------------
__global__ void split_kernel(const float* __restrict__ in,
                             bf16* __restrict__ hi, bf16* __restrict__ lo,
                             int n4)
{
    int i = blockIdx.x * blockDim.x + threadIdx.x;
    if (i >= n4) return;
    float4 v = reinterpret_cast<const float4*>(in)[i];
    __nv_bfloat162 h0 = __floats2bfloat162_rn(v.x, v.y);
    __nv_bfloat162 h1 = __floats2bfloat162_rn(v.z, v.w);
    float2 f0 = __bfloat1622float2(h0);
    float2 f1 = __bfloat1622float2(h1);
    __nv_bfloat162 l0 = __floats2bfloat162_rn(v.x - f0.x, v.y - f0.y);
    __nv_bfloat162 l1 = __floats2bfloat162_rn(v.z - f1.x, v.w - f1.y);
    reinterpret_cast<__nv_bfloat162*>(hi)[2 * i]     = h0;
    reinterpret_cast<__nv_bfloat162*>(hi)[2 * i + 1] = h1;
    reinterpret_cast<__nv_bfloat162*>(lo)[2 * i]     = l0;
    reinterpret_cast<__nv_bfloat162*>(lo)[2 * i + 1] = l1;
}

// ---------------- split-bf16 GEMM, cp.async double-buffered ---------------
// C[M,N] = A[M,K] @ W[N,K]^T + bias;  Ah*Wh + Ah*Wl + Al*Wh.
// 256 threads (8 warps 4m x 2n), BM=256, BN=128, BK=32; warp tile 64x64.
// dyn smem: sA[2][2][256][40] (81920 B), sB[2][2][128][40] (40960 B)
#define GA(buf,p,r,c) (smp         + (((buf)*2 + (p)) * 256 + (r)) * 40 + (c))
#define GB(buf,p,r,c) (smp + 40960 + (((buf)*2 + (p)) * 128 + (r)) * 40 + (c))
#define G_SMEM 122880

template<bool SPLIT_OUT>
__global__ __launch_bounds__(256, 1) void gemm_mma(
    const bf16* __restrict__ Ah, const bf16* __restrict__ Al,
    const bf16* __restrict__ Bh, const bf16* __restrict__ Bl,
    const float* __restrict__ bias,
    float* __restrict__ Cf, bf16* __restrict__ Ch, bf16* __restrict__ Cl,
    int M, int N, int K)
{
    extern __shared__ __align__(16) bf16 smp[];

    const int tid  = threadIdx.x;
    const int warp = tid >> 5;
    const int lane = tid & 31;
    const int g = lane >> 2;
    const int t = lane & 3;
    const int wm = (warp >> 1) * 64;      // warp m offset (0,64,128,192)
    const int wn = (warp & 1) * 64;       // warp n offset (0,64)
    const int bm = blockIdx.y * 256;
    const int bn = blockIdx.x * 128;

    // ldmatrix lane -> (row, col) offsets
    const int lq = lane >> 3, lr = lane & 7;
    const int a_ro = (lq & 1) * 8, a_co = (lq >> 1) * 8;
    const int b_ro = (lq >> 1) * 8, b_co = (lq & 1) * 8;

    float acc[4][8][4] = {};
    const int iters = K / 32;

    auto load_tiles = [&](int s, int k0) {
        #pragma unroll
        for (int i = 0; i < 4; i++) {           // A: 256 rows x 4 chunks
            int idx = tid + i * 256;
            int r = idx >> 2, cc = (idx & 3) * 8;
            const size_t go = (size_t)(bm + r) * K + k0 + cc;
            cp16(GA(s,0,r,cc), Ah + go);
            cp16(GA(s,1,r,cc), Al + go);
        }
        #pragma unroll
        for (int i = 0; i < 2; i++) {           // B: 128 rows x 4 chunks
            int idx = tid + i * 256;
            int r = idx >> 2, cc = (idx & 3) * 8;
            const size_t go = (size_t)(bn + r) * K + k0 + cc;
            cp16(GB(s,0,r,cc), Bh + go);
            cp16(GB(s,1,r,cc), Bl + go);
        }
        cp_commit();
    };

    load_tiles(0, 0);

    for (int it = 0; it < iters; it++) {
        if (it + 1 < iters) {
            load_tiles((it + 1) & 1, (it + 1) * 32);
            cp_wait<1>();
        } else {
            cp_wait<0>();
        }
        __syncthreads();

        const int buf = it & 1;
        #pragma unroll
        for (int kk = 0; kk < 32; kk += 16) {
            uint32_t a[2][4][4];               // [p][mt][frag]
            #pragma unroll
            for (int mt = 0; mt < 4; mt++) {
                ldsm4(a[0][mt], GA(buf,0, wm + mt*16 + a_ro + lr, kk + a_co));
                ldsm4(a[1][mt], GA(buf,1, wm + mt*16 + a_ro + lr, kk + a_co));
            }
            #pragma unroll
            for (int ntp = 0; ntp < 4; ntp++) {
                uint32_t rh[4], rl[4];
                ldsm4(rh, GB(buf,0, wn + ntp*16 + b_ro + lr, kk + b_co));
                ldsm4(rl, GB(buf,1, wn + ntp*16 + b_ro + lr, kk + b_co));
                #pragma unroll
                for (int hv = 0; hv < 2; hv++) {
                    const int nt = 2*ntp + hv;
                    const uint32_t bh0 = rh[2*hv], bh1 = rh[2*hv+1];
                    const uint32_t bl0 = rl[2*hv], bl1 = rl[2*hv+1];
                    #pragma unroll
                    for (int mt = 0; mt < 4; mt++) {
                        mma16816(acc[mt][nt], a[0][mt], bh0, bh1);
                        mma16816(acc[mt][nt], a[0][mt], bl0, bl1);
                        mma16816(acc[mt][nt], a[1][mt], bh0, bh1);
                    }
                }
            }
        }
        __syncthreads();
    }

    // epilogue
    #pragma unroll
    for (int mt = 0; mt < 4; mt++) {
        #pragma unroll
        for (int nt = 0; nt < 8; nt++) {
            const int row = bm + wm + mt*16 + g;
            const int col = bn + wn + nt*8 + 2*t;
            float2 bs = *(const float2*)&bias[col];
            float v0 = acc[mt][nt][0] + bs.x;
            float v1 = acc[mt][nt][1] + bs.y;
            float v2 = acc[mt][nt][2] + bs.x;
            float v3 = acc[mt][nt][3] + bs.y;
            if (SPLIT_OUT) {
                uint32_t hh, ll;
                split2(v0, v1, hh, ll);
                *(uint32_t*)&Ch[(size_t)row * N + col] = hh;
                *(uint32_t*)&Cl[(size_t)row * N + col] = ll;
                split2(v2, v3, hh, ll);
                *(uint32_t*)&Ch[(size_t)(row + 8) * N + col] = hh;
                *(uint32_t*)&Cl[(size_t)(row + 8) * N + col] = ll;
            } else {
                *(float2*)&Cf[(size_t)row * N + col]       = make_float2(v0, v1);
                *(float2*)&Cf[(size_t)(row + 8) * N + col] = make_float2(v2, v3);
            }
        }
    }
}

// ---------------- flash attention: Q tile 256, 32 rows/warp ----------------
// 256 threads (8 warps). Q (pre-scaled) in smem; K/V double-buffered cp.async.
// smem elems: Q[2][256][72] | K[2][2][64][72] | V[2][2][64][72] = 147456 B
#define SQ(p,r,c)     (smp +         ((p) * 256 + (r)) * 72 + (c))
#define AK(buf,p,r,c) (smp + 36864 + (((buf)*2 + (p)) * 64 + (r)) * 72 + (c))
#define AV(buf,p,r,c) (smp + 55296 + (((buf)*2 + (p)) * 64 + (r)) * 72 + (c))
#define ATTN_SMEM 147456

__global__ __launch_bounds__(256, 1) void attn_mma(
    const bf16* __restrict__ qh, const bf16* __restrict__ ql,
    bf16* __restrict__ yh, bf16* __restrict__ yl)
{
    extern __shared__ __align__(16) bf16 smp[];

    const int tid  = threadIdx.x;
    const int warp = tid >> 5;
    const int lane = tid & 31;
    const int g = lane >> 2;
    const int t = lane & 3;
    const int h = blockIdx.y;
    const int b = blockIdx.z;
    const int qoff = h * HEAD_DIM;
    const int qbase = b * SEQ + blockIdx.x * 256;

    const int crow = tid >> 2;            // 0..63 (K/V loader)
    const int cseg = (tid & 3) * 16;

    const int lq = lane >> 3, lr = lane & 7;
    const int a_ro = (lq & 1) * 8, a_co = (lq >> 1) * 8;   // Q frag (A)
    const int k_ro = (lq >> 1) * 8, k_co = (lq & 1) * 8;   // K frag (B)
    const int v_ro = (lq & 1) * 8,  v_co = (lq >> 1) * 8;  // V frag (B, trans)

    // ---- fill Q smem (pre-scaled by 0.125, exact in bf16) ----
    {
        const uint32_t sc = 0x3E003E00u;
        const size_t base = (size_t)(qbase + tid) * QKV_COLS + qoff;
        #pragma unroll
        for (int c = 0; c < 64; c += 8) {
            uint4 vh = *(const uint4*)&qh[base + c];
            uint4 vl = *(const uint4*)&ql[base + c];
            uint32_t* ph = (uint32_t*)&vh;
            uint32_t* pl = (uint32_t*)&vl;
            #pragma unroll
            for (int j = 0; j < 4; j++) {
                ph[j] = bf2_mul(ph[j], sc);
                pl[j] = bf2_mul(pl[j], sc);
            }
            *(uint4*)SQ(0, tid, c) = vh;
            *(uint4*)SQ(1, tid, c) = vl;
        }
    }

    float o[2][8][4] = {};
    float mx[2][2] = {{-1e30f,-1e30f},{-1e30f,-1e30f}};
    float ls[2][2] = {};

    auto load_tile = [&](int kt, int buf) {
        const size_t base = (size_t)(b * SEQ + kt * 64 + crow) * QKV_COLS
                          + qoff + cseg;
        const bf16* skh = qh + base + N_EMBD;
        const bf16* skl = ql + base + N_EMBD;
        const bf16* svh = qh + base + 2 * N_EMBD;
        const bf16* svl = ql + base + 2 * N_EMBD;
        cp16(AK(buf,0,crow,cseg), skh);  cp16(AK(buf,0,crow,cseg+8), skh+8);
        cp16(AK(buf,1,crow,cseg), skl);  cp16(AK(buf,1,crow,cseg+8), skl+8);
        cp16(AV(buf,0,crow,cseg), svh);  cp16(AV(buf,0,crow,cseg+8), svh+8);
        cp16(AV(buf,1,crow,cseg), svl);  cp16(AV(buf,1,crow,cseg+8), svl+8);
        cp_commit();
    };

    load_tile(0, 0);

    const int NT = SEQ / 64;
    for (int kt = 0; kt < NT; kt++) {
        if (kt + 1 < NT) { load_tile(kt + 1, (kt + 1) & 1); cp_wait<1>(); }
        else             { cp_wait<0>(); }
        __syncthreads();
        const int buf = kt & 1;

        // ---- S = Qs @ K^T (32 rows/warp) ----
        float s[2][8][4] = {};
        #pragma unroll
        for (int kk = 0; kk < 4; kk++) {
            uint32_t qa[2][2][4];
            #pragma unroll
            for (int mt = 0; mt < 2; mt++) {
                ldsm4(qa[0][mt], SQ(0, warp*32 + mt*16 + a_ro + lr, kk*16 + a_co));
                ldsm4(qa[1][mt], SQ(1, warp*32 + mt*16 + a_ro + lr, kk*16 + a_co));
            }
            #pragma unroll
            for (int ntp = 0; ntp < 4; ntp++) {
                uint32_t rh[4], rl[4];
                ldsm4(rh, AK(buf,0, ntp*16 + k_ro + lr, kk*16 + k_co));
                ldsm4(rl, AK(buf,1, ntp*16 + k_ro + lr, kk*16 + k_co));
                #pragma unroll
                for (int hv = 0; hv < 2; hv++) {
                    const int nt = 2*ntp + hv;
                    #pragma unroll
                    for (int mt = 0; mt < 2; mt++) {
                        mma16816(s[mt][nt], qa[0][mt], rh[2*hv], rh[2*hv+1]);
                        mma16816(s[mt][nt], qa[0][mt], rl[2*hv], rl[2*hv+1]);
                        mma16816(s[mt][nt], qa[1][mt], rh[2*hv], rh[2*hv+1]);
                    }
                }
            }
        }

        // ---- online softmax + P split ----
        uint32_t ah[2][4][4], alo[2][4][4];
        #pragma unroll
        for (int mt = 0; mt < 2; mt++) {
            float r0 = -1e30f, r1 = -1e30f;
            #pragma unroll
            for (int nt = 0; nt < 8; nt++) {
                r0 = fmaxf(r0, fmaxf(s[mt][nt][0], s[mt][nt][1]));
                r1 = fmaxf(r1, fmaxf(s[mt][nt][2], s[mt][nt][3]));
            }
            r0 = fmaxf(r0, __shfl_xor_sync(0xffffffffu, r0, 1));
            r0 = fmaxf(r0, __shfl_xor_sync(0xffffffffu, r0, 2));
            r1 = fmaxf(r1, __shfl_xor_sync(0xffffffffu, r1, 1));
            r1 = fmaxf(r1, __shfl_xor_sync(0xffffffffu, r1, 2));

            const float mn0 = fmaxf(mx[mt][0], r0);
            const float mn1 = fmaxf(mx[mt][1], r1);
            const float a0 = __expf(mx[mt][0] - mn0);
            const float a1 = __expf(mx[mt][1] - mn1);
            mx[mt][0] = mn0; mx[mt][1] = mn1;
            #pragma unroll
            for (int nt = 0; nt < 8; nt++) {
                o[mt][nt][0] *= a0; o[mt][nt][1] *= a0;
                o[mt][nt][2] *= a1; o[mt][nt][3] *= a1;
            }
            float t0 = 0.f, t1 = 0.f;
            #pragma unroll
            for (int nt = 0; nt < 8; nt++) {
                const float p0 = __expf(s[mt][nt][0] - mn0);
                const float p1 = __expf(s[mt][nt][1] - mn0);
                const float p2 = __expf(s[mt][nt][2] - mn1);
                const float p3 = __expf(s[mt][nt][3] - mn1);
                t0 += p0 + p1;
                t1 += p2 + p3;
                const int kc = nt >> 1, hf = nt & 1;
                split2(p0, p1, ah[mt][kc][hf ? 2 : 0], alo[mt][kc][hf ? 2 : 0]);
                split2(p2, p3, ah[mt][kc][hf ? 3 : 1], alo[mt][kc][hf ? 3 : 1]);
            }
            t0 += __shfl_xor_sync(0xffffffffu, t0, 1);
            t0 += __shfl_xor_sync(0xffffffffu, t0, 2);
            t1 += __shfl_xor_sync(0xffffffffu, t1, 1);
            t1 += __shfl_xor_sync(0xffffffffu, t1, 2);
            ls[mt][0] = ls[mt][0] * a0 + t0;
            ls[mt][1] = ls[mt][1] * a1 + t1;
        }

        // ---- O += P @ V ----
        #pragma unroll
        for (int kc = 0; kc < 4; kc++) {
            #pragma unroll
            for (int dtp = 0; dtp < 4; dtp++) {
                uint32_t rh[4], rl[4];
                ldsm4t(rh, AV(buf,0, kc*16 + v_ro + lr, dtp*16 + v_co));
                ldsm4t(rl, AV(buf,1, kc*16 + v_ro + lr, dtp*16 + v_co));
                #pragma unroll
                for (int hv = 0; hv < 2; hv++) {
                    const int nt = 2*dtp + hv;
                    #pragma unroll
                    for (int mt = 0; mt < 2; mt++) {
                        mma16816(o[mt][nt], ah[mt][kc],  rh[2*hv], rh[2*hv+1]);
                        mma16816(o[mt][nt], ah[mt][kc],  rl[2*hv], rl[2*hv+1]);
                        mma16816(o[mt][nt], alo[mt][kc], rh[2*hv], rh[2*hv+1]);
                    }
                }
            }
        }
        __syncthreads();
    }

    // ---- normalize + split + store ----
    #pragma unroll
    for (int mt = 0; mt < 2; mt++) {
        const float inv0 = 1.f / ls[mt][0], inv1 = 1.f / ls[mt][1];
        const int grow = qbase + warp*32 + mt*16;
        #pragma unroll
        for (int nt = 0; nt < 8; nt++) {
            const int col = qoff + nt * 8 + 2 * t;
            size_t r0 = (size_t)(grow + g)     * N_EMBD + col;
            size_t r1 = (size_t)(grow + g + 8) * N_EMBD + col;
            uint32_t hh, ll;
            split2(o[mt][nt][0] * inv0, o[mt][nt][1] * inv0, hh, ll);
            *(uint32_t*)&yh[r0] = hh;
            *(uint32_t*)&yl[r0] = ll;
            split2(o[mt][nt][2] * inv1, o[mt][nt][3] * inv1, hh, ll);
            *(uint32_t*)&yh[r1] = hh;
            *(uint32_t*)&yl[r1] = ll;
        }
    }
}

// ---------------------------------------------------------------------------
extern "C" void kernel_launch(void* const* d_in, const int* in_sizes, int n_in,
                              void* d_out, int out_size)
{
    const float* x      = (const float*)d_in[0];
    const float* W_attn = (const float*)d_in[1];
    const float* b_attn = (const float*)d_in[2];
    const float* W_proj = (const float*)d_in[3];
    const float* b_proj = (const float*)d_in[4];
    float* out = (float*)d_out;

    bf16 *xh, *xl, *Wah, *Wal, *Wph, *Wpl, *qkvh, *qkvl, *yh, *yl;
    cudaGetSymbolAddress((void**)&xh,  g_xh);
    cudaGetSymbolAddress((void**)&xl,  g_xl);
    cudaGetSymbolAddress((void**)&Wah, g_Wah);
    cudaGetSymbolAddress((void**)&Wal, g_Wal);
    cudaGetSymbolAddress((void**)&Wph, g_Wph);
    cudaGetSymbolAddress((void**)&Wpl, g_Wpl);
    cudaGetSymbolAddress((void**)&qkvh, g_qkvh);
    cudaGetSymbolAddress((void**)&qkvl, g_qkvl);
    cudaGetSymbolAddress((void**)&yh,  g_yh);
    cudaGetSymbolAddress((void**)&yl,  g_yl);

    cudaFuncSetAttribute(gemm_mma<true>,
        cudaFuncAttributeMaxDynamicSharedMemorySize, G_SMEM);
    cudaFuncSetAttribute(gemm_mma<false>,
        cudaFuncAttributeMaxDynamicSharedMemorySize, G_SMEM);
    cudaFuncSetAttribute(attn_mma,
        cudaFuncAttributeMaxDynamicSharedMemorySize, ATTN_SMEM);

    // split inputs to bf16 hi/lo
    {
        int n4 = ROWS * N_EMBD / 4;
        split_kernel<<<(n4 + 255) / 256, 256>>>(x, xh, xl, n4);
        n4 = QKV_COLS * N_EMBD / 4;
        split_kernel<<<(n4 + 255) / 256, 256>>>(W_attn, Wah, Wal, n4);
        n4 = N_EMBD * N_EMBD / 4;
        split_kernel<<<(n4 + 255) / 256, 256>>>(W_proj, Wph, Wpl, n4);
    }

    // 1) qkv = x @ W_attn^T + b_attn  (epilogue splits to bf16 hi/lo)
    {
        dim3 grid(QKV_COLS / 128, ROWS / 256);
        gemm_mma<true><<<grid, 256, G_SMEM>>>(xh, xl, Wah, Wal, b_attn,
                                              nullptr, qkvh, qkvl,
                                              ROWS, QKV_COLS, N_EMBD);
    }

    // 2) flash attention
    {
        dim3 grid(SEQ / 256, N_HEAD, BATCH);
        attn_mma<<<grid, 256, ATTN_SMEM>>>(qkvh, qkvl, yh, yl);
    }

    // 3) out = y @ W_proj^T + b_proj  (fp32 output)
    {
        dim3 grid(N_EMBD / 128, ROWS / 256);
        gemm_mma<false><<<grid, 256, G_SMEM>>>(yh, yl, Wph, Wpl, b_proj,
                                               out, nullptr, nullptr,
                                               ROWS, N_EMBD, N_EMBD);
    }
}

// round 10
// speedup vs baseline: 5.4412x; 1.0407x over previous
#include <cuda_runtime.h>
#include <cuda_bf16.h>
#include <cstdint>

#define N_EMBD   768
#define N_HEAD   12
#define HEAD_DIM 64
#define BATCH    2
#define SEQ      4096
#define QKV_COLS 2304
#define ROWS     8192

typedef __nv_bfloat16 bf16;

// ---------------- scratch (device globals; no cudaMalloc allowed) ----------
__device__ bf16 g_xh [(size_t)ROWS * N_EMBD];
__device__ bf16 g_xl [(size_t)ROWS * N_EMBD];
__device__ bf16 g_Wah[(size_t)QKV_COLS * N_EMBD];
__device__ bf16 g_Wal[(size_t)QKV_COLS * N_EMBD];
__device__ bf16 g_Wph[(size_t)N_EMBD * N_EMBD];
__device__ bf16 g_Wpl[(size_t)N_EMBD * N_EMBD];
__device__ bf16 g_qkvh[(size_t)ROWS * QKV_COLS];
__device__ bf16 g_qkvl[(size_t)ROWS * QKV_COLS];
__device__ bf16 g_yh [(size_t)ROWS * N_EMBD];
__device__ bf16 g_yl [(size_t)ROWS * N_EMBD];

// ---------------- low-level helpers ----------------------------------------
__device__ __forceinline__ uint32_t smem_u32(const void* p) {
    return (uint32_t)__cvta_generic_to_shared(p);
}
__device__ __forceinline__ void cp16(const void* s, const void* g) {
    asm volatile("cp.async.cg.shared.global [%0], [%1], 16;"
                 :: "r"(smem_u32(s)), "l"(g));
}
__device__ __forceinline__ void cp_commit() {
    asm volatile("cp.async.commit_group;");
}
template<int N> __device__ __forceinline__ void cp_wait() {
    asm volatile("cp.async.wait_group %0;" :: "n"(N));
}
__device__ __forceinline__ void ldsm4(uint32_t* r, const void* p) {
    asm volatile("ldmatrix.sync.aligned.m8n8.x4.shared.b16 {%0,%1,%2,%3}, [%4];"
                 : "=r"(r[0]), "=r"(r[1]), "=r"(r[2]), "=r"(r[3])
                 : "r"(smem_u32(p)));
}
__device__ __forceinline__ void ldsm4t(uint32_t* r, const void* p) {
    asm volatile("ldmatrix.sync.aligned.m8n8.x4.trans.shared.b16 {%0,%1,%2,%3}, [%4];"
                 : "=r"(r[0]), "=r"(r[1]), "=r"(r[2]), "=r"(r[3])
                 : "r"(smem_u32(p)));
}
__device__ __forceinline__ void mma16816(float* c, const uint32_t* a,
                                         uint32_t b0, uint32_t b1)
{
    asm volatile(
        "mma.sync.aligned.m16n8k16.row.col.f32.bf16.bf16.f32 "
        "{%0,%1,%2,%3},{%4,%5,%6,%7},{%8,%9},{%0,%1,%2,%3};"
        : "+f"(c[0]), "+f"(c[1]), "+f"(c[2]), "+f"(c[3])
        : "r"(a[0]), "r"(a[1]), "r"(a[2]), "r"(a[3]), "r"(b0), "r"(b1));
}
__device__ __forceinline__ void split2(float v0, float v1,
                                       uint32_t& h, uint32_t& l)
{
    __nv_bfloat162 h2 = __floats2bfloat162_rn(v0, v1);
    float2 f = __bfloat1622float2(h2);
    __nv_bfloat162 l2 = __floats2bfloat162_rn(v0 - f.x, v1 - f.y);
    h = *reinterpret_cast<uint32_t*>(&h2);
    l = *reinterpret_cast<uint32_t*>(&l2);
}
__device__ __forceinline__ uint32_t bf2_mul(uint32_t a, uint32_t s)
{
    __nv_bfloat162 av = *reinterpret_cast<__nv_bfloat162*>(&a);
    __nv_bfloat162 sv = *reinterpret_cast<__nv_bfloat162*>(&s);
    __nv_bfloat162 r = __hmul2(av, sv);
    return *reinterpret_cast<uint32_t*>(&r);
}

// ---------------- fp32 -> (bf16 hi, bf16 lo) split -------------------------
__global__ void split_kernel(const float* __restrict__ in,
                             bf16* __restrict__ hi, bf16* __restrict__ lo,
                             int n4)
{
    int i = blockIdx.x * blockDim.x + threadIdx.x;
    if (i >= n4) return;
    float4 v = reinterpret_cast<const float4*>(in)[i];
    __nv_bfloat162 h0 = __floats2bfloat162_rn(v.x, v.y);
    __nv_bfloat162 h1 = __floats2bfloat162_rn(v.z, v.w);
    float2 f0 = __bfloat1622float2(h0);
    float2 f1 = __bfloat1622float2(h1);
    __nv_bfloat162 l0 = __floats2bfloat162_rn(v.x - f0.x, v.y - f0.y);
    __nv_bfloat162 l1 = __floats2bfloat162_rn(v.z - f1.x, v.w - f1.y);
    reinterpret_cast<__nv_bfloat162*>(hi)[2 * i]     = h0;
    reinterpret_cast<__nv_bfloat162*>(hi)[2 * i + 1] = h1;
    reinterpret_cast<__nv_bfloat162*>(lo)[2 * i]     = l0;
    reinterpret_cast<__nv_bfloat162*>(lo)[2 * i + 1] = l1;
}

// ---------------- split-bf16 GEMM: 128 thr, 2 CTAs/SM ----------------------
// C[M,N] = A[M,K] @ W[N,K]^T + bias;  Ah*Wh + Ah*Wl + Al*Wh.
// 128 threads (4 warps 2m x 2n), BM=128, BN=128, BK=32; warp tile 64x64.
// dyn smem: sA[2][2][128][40] (40960 B) + sB same = 81920 B -> 2 CTAs/SM.
#define GA(buf,p,r,c) (smp         + (((buf)*2 + (p)) * 128 + (r)) * 40 + (c))
#define GB(buf,p,r,c) (smp + 20480 + (((buf)*2 + (p)) * 128 + (r)) * 40 + (c))
#define G_SMEM 81920

template<bool SPLIT_OUT>
__global__ __launch_bounds__(128, 2) void gemm_mma(
    const bf16* __restrict__ Ah, const bf16* __restrict__ Al,
    const bf16* __restrict__ Bh, const bf16* __restrict__ Bl,
    const float* __restrict__ bias,
    float* __restrict__ Cf, bf16* __restrict__ Ch, bf16* __restrict__ Cl,
    int M, int N, int K)
{
    extern __shared__ __align__(16) bf16 smp[];

    const int tid  = threadIdx.x;
    const int warp = tid >> 5;
    const int lane = tid & 31;
    const int g = lane >> 2;
    const int t = lane & 3;
    const int wm = (warp >> 1) * 64;
    const int wn = (warp & 1) * 64;
    const int bm = blockIdx.y * 128;
    const int bn = blockIdx.x * 128;

    const int lq = lane >> 3, lr = lane & 7;
    const int a_ro = (lq & 1) * 8, a_co = (lq >> 1) * 8;
    const int b_ro = (lq >> 1) * 8, b_co = (lq & 1) * 8;

    float acc[4][8][4] = {};
    const int iters = K / 32;

    auto load_tiles = [&](int s, int k0) {
        #pragma unroll
        for (int i = 0; i < 4; i++) {           // 128 rows x 4 chunks each
            int idx = tid + i * 128;
            int r = idx >> 2, cc = (idx & 3) * 8;
            const size_t goa = (size_t)(bm + r) * K + k0 + cc;
            const size_t gob = (size_t)(bn + r) * K + k0 + cc;
            cp16(GA(s,0,r,cc), Ah + goa);
            cp16(GA(s,1,r,cc), Al + goa);
            cp16(GB(s,0,r,cc), Bh + gob);
            cp16(GB(s,1,r,cc), Bl + gob);
        }
        cp_commit();
    };

    load_tiles(0, 0);

    for (int it = 0; it < iters; it++) {
        if (it + 1 < iters) {
            load_tiles((it + 1) & 1, (it + 1) * 32);
            cp_wait<1>();
        } else {
            cp_wait<0>();
        }
        __syncthreads();

        const int buf = it & 1;
        #pragma unroll
        for (int kk = 0; kk < 32; kk += 16) {
            uint32_t a[2][4][4];
            #pragma unroll
            for (int mt = 0; mt < 4; mt++) {
                ldsm4(a[0][mt], GA(buf,0, wm + mt*16 + a_ro + lr, kk + a_co));
                ldsm4(a[1][mt], GA(buf,1, wm + mt*16 + a_ro + lr, kk + a_co));
            }
            #pragma unroll
            for (int ntp = 0; ntp < 4; ntp++) {
                uint32_t rh[4], rl[4];
                ldsm4(rh, GB(buf,0, wn + ntp*16 + b_ro + lr, kk + b_co));
                ldsm4(rl, GB(buf,1, wn + ntp*16 + b_ro + lr, kk + b_co));
                #pragma unroll
                for (int hv = 0; hv < 2; hv++) {
                    const int nt = 2*ntp + hv;
                    const uint32_t bh0 = rh[2*hv], bh1 = rh[2*hv+1];
                    const uint32_t bl0 = rl[2*hv], bl1 = rl[2*hv+1];
                    #pragma unroll
                    for (int mt = 0; mt < 4; mt++) {
                        mma16816(acc[mt][nt], a[0][mt], bh0, bh1);
                        mma16816(acc[mt][nt], a[0][mt], bl0, bl1);
                        mma16816(acc[mt][nt], a[1][mt], bh0, bh1);
                    }
                }
            }
        }
        __syncthreads();
    }

    // epilogue (warp tile is 64 rows: mt covers wm + mt*16)
    #pragma unroll
    for (int mt = 0; mt < 4; mt++) {
        #pragma unroll
        for (int nt = 0; nt < 8; nt++) {
            const int row = bm + wm + mt*16 + g;
            const int col = bn + wn + nt*8 + 2*t;
            float2 bs = *(const float2*)&bias[col];
            float v0 = acc[mt][nt][0] + bs.x;
            float v1 = acc[mt][nt][1] + bs.y;
            float v2 = acc[mt][nt][2] + bs.x;
            float v3 = acc[mt][nt][3] + bs.y;
            if (SPLIT_OUT) {
                uint32_t hh, ll;
                split2(v0, v1, hh, ll);
                *(uint32_t*)&Ch[(size_t)row * N + col] = hh;
                *(uint32_t*)&Cl[(size_t)row * N + col] = ll;
                split2(v2, v3, hh, ll);
                *(uint32_t*)&Ch[(size_t)(row + 8) * N + col] = hh;
                *(uint32_t*)&Cl[(size_t)(row + 8) * N + col] = ll;
            } else {
                *(float2*)&Cf[(size_t)row * N + col]       = make_float2(v0, v1);
                *(float2*)&Cf[(size_t)(row + 8) * N + col] = make_float2(v2, v3);
            }
        }
    }
}

// ---------------- flash attention: 128 thr, Q tile 128, 2 CTAs/SM ----------
// 4 warps, 32 Q-rows/warp. Q (pre-scaled) in smem; K/V double-buffered.
// smem elems: Q[2][128][72] | K[2][2][64][72] | V[2][2][64][72]
//   = 18432 + 18432 + 18432 elems = 110592 B -> 2 CTAs/SM.
#define SQ(p,r,c)     (smp +         ((p) * 128 + (r)) * 72 + (c))
#define AK(buf,p,r,c) (smp + 18432 + (((buf)*2 + (p)) * 64 + (r)) * 72 + (c))
#define AV(buf,p,r,c) (smp + 36864 + (((buf)*2 + (p)) * 64 + (r)) * 72 + (c))
#define ATTN_SMEM 110592

__global__ __launch_bounds__(128, 2) void attn_mma(
    const bf16* __restrict__ qh, const bf16* __restrict__ ql,
    bf16* __restrict__ yh, bf16* __restrict__ yl)
{
    extern __shared__ __align__(16) bf16 smp[];

    const int tid  = threadIdx.x;
    const int warp = tid >> 5;
    const int lane = tid & 31;
    const int g = lane >> 2;
    const int t = lane & 3;
    const int h = blockIdx.y;
    const int b = blockIdx.z;
    const int qoff = h * HEAD_DIM;
    const int qbase = b * SEQ + blockIdx.x * 128;

    const int lq = lane >> 3, lr = lane & 7;
    const int a_ro = (lq & 1) * 8, a_co = (lq >> 1) * 8;
    const int k_ro = (lq >> 1) * 8, k_co = (lq & 1) * 8;
    const int v_ro = (lq & 1) * 8,  v_co = (lq >> 1) * 8;

    // ---- fill Q smem (pre-scaled by 0.125, exact in bf16) ----
    {
        const uint32_t sc = 0x3E003E00u;
        const size_t base = (size_t)(qbase + tid) * QKV_COLS + qoff;
        #pragma unroll
        for (int c = 0; c < 64; c += 8) {
            uint4 vh = *(const uint4*)&qh[base + c];
            uint4 vl = *(const uint4*)&ql[base + c];
            uint32_t* ph = (uint32_t*)&vh;
            uint32_t* pl = (uint32_t*)&vl;
            #pragma unroll
            for (int j = 0; j < 4; j++) {
                ph[j] = bf2_mul(ph[j], sc);
                pl[j] = bf2_mul(pl[j], sc);
            }
            *(uint4*)SQ(0, tid, c) = vh;
            *(uint4*)SQ(1, tid, c) = vl;
        }
    }

    float o[2][8][4] = {};
    float mx[2][2] = {{-1e30f,-1e30f},{-1e30f,-1e30f}};
    float ls[2][2] = {};

    auto load_tile = [&](int kt, int buf) {
        #pragma unroll
        for (int i = 0; i < 2; i++) {
            int idx = tid + i * 128;
            int crow = idx >> 2, cseg = (idx & 3) * 16;
            const size_t base = (size_t)(b * SEQ + kt * 64 + crow) * QKV_COLS
                              + qoff + cseg;
            const bf16* skh = qh + base + N_EMBD;
            const bf16* skl = ql + base + N_EMBD;
            const bf16* svh = qh + base + 2 * N_EMBD;
            const bf16* svl = ql + base + 2 * N_EMBD;
            cp16(AK(buf,0,crow,cseg), skh);  cp16(AK(buf,0,crow,cseg+8), skh+8);
            cp16(AK(buf,1,crow,cseg), skl);  cp16(AK(buf,1,crow,cseg+8), skl+8);
            cp16(AV(buf,0,crow,cseg), svh);  cp16(AV(buf,0,crow,cseg+8), svh+8);
            cp16(AV(buf,1,crow,cseg), svl);  cp16(AV(buf,1,crow,cseg+8), svl+8);
        }
        cp_commit();
    };

    load_tile(0, 0);

    const int NT = SEQ / 64;
    for (int kt = 0; kt < NT; kt++) {
        if (kt + 1 < NT) { load_tile(kt + 1, (kt + 1) & 1); cp_wait<1>(); }
        else             { cp_wait<0>(); }
        __syncthreads();
        const int buf = kt & 1;

        // ---- S = Qs @ K^T (32 rows/warp) ----
        float s[2][8][4] = {};
        #pragma unroll
        for (int kk = 0; kk < 4; kk++) {
            uint32_t qa[2][2][4];
            #pragma unroll
            for (int mt = 0; mt < 2; mt++) {
                ldsm4(qa[0][mt], SQ(0, warp*32 + mt*16 + a_ro + lr, kk*16 + a_co));
                ldsm4(qa[1][mt], SQ(1, warp*32 + mt*16 + a_ro + lr, kk*16 + a_co));
            }
            #pragma unroll
            for (int ntp = 0; ntp < 4; ntp++) {
                uint32_t rh[4], rl[4];
                ldsm4(rh, AK(buf,0, ntp*16 + k_ro + lr, kk*16 + k_co));
                ldsm4(rl, AK(buf,1, ntp*16 + k_ro + lr, kk*16 + k_co));
                #pragma unroll
                for (int hv = 0; hv < 2; hv++) {
                    const int nt = 2*ntp + hv;
                    #pragma unroll
                    for (int mt = 0; mt < 2; mt++) {
                        mma16816(s[mt][nt], qa[0][mt], rh[2*hv], rh[2*hv+1]);
                        mma16816(s[mt][nt], qa[0][mt], rl[2*hv], rl[2*hv+1]);
                        mma16816(s[mt][nt], qa[1][mt], rh[2*hv], rh[2*hv+1]);
                    }
                }
            }
        }

        // ---- online softmax + P split ----
        uint32_t ah[2][4][4], alo[2][4][4];
        #pragma unroll
        for (int mt = 0; mt < 2; mt++) {
            float r0 = -1e30f, r1 = -1e30f;
            #pragma unroll
            for (int nt = 0; nt < 8; nt++) {
                r0 = fmaxf(r0, fmaxf(s[mt][nt][0], s[mt][nt][1]));
                r1 = fmaxf(r1, fmaxf(s[mt][nt][2], s[mt][nt][3]));
            }
            r0 = fmaxf(r0, __shfl_xor_sync(0xffffffffu, r0, 1));
            r0 = fmaxf(r0, __shfl_xor_sync(0xffffffffu, r0, 2));
            r1 = fmaxf(r1, __shfl_xor_sync(0xffffffffu, r1, 1));
            r1 = fmaxf(r1, __shfl_xor_sync(0xffffffffu, r1, 2));

            const float mn0 = fmaxf(mx[mt][0], r0);
            const float mn1 = fmaxf(mx[mt][1], r1);
            const float a0 = __expf(mx[mt][0] - mn0);
            const float a1 = __expf(mx[mt][1] - mn1);
            mx[mt][0] = mn0; mx[mt][1] = mn1;
            #pragma unroll
            for (int nt = 0; nt < 8; nt++) {
                o[mt][nt][0] *= a0; o[mt][nt][1] *= a0;
                o[mt][nt][2] *= a1; o[mt][nt][3] *= a1;
            }
            float t0 = 0.f, t1 = 0.f;
            #pragma unroll
            for (int nt = 0; nt < 8; nt++) {
                const float p0 = __expf(s[mt][nt][0] - mn0);
                const float p1 = __expf(s[mt][nt][1] - mn0);
                const float p2 = __expf(s[mt][nt][2] - mn1);
                const float p3 = __expf(s[mt][nt][3] - mn1);
                t0 += p0 + p1;
                t1 += p2 + p3;
                const int kc = nt >> 1, hf = nt & 1;
                split2(p0, p1, ah[mt][kc][hf ? 2 : 0], alo[mt][kc][hf ? 2 : 0]);
                split2(p2, p3, ah[mt][kc][hf ? 3 : 1], alo[mt][kc][hf ? 3 : 1]);
            }
            t0 += __shfl_xor_sync(0xffffffffu, t0, 1);
            t0 += __shfl_xor_sync(0xffffffffu, t0, 2);
            t1 += __shfl_xor_sync(0xffffffffu, t1, 1);
            t1 += __shfl_xor_sync(0xffffffffu, t1, 2);
            ls[mt][0] = ls[mt][0] * a0 + t0;
            ls[mt][1] = ls[mt][1] * a1 + t1;
        }

        // ---- O += P @ V ----
        #pragma unroll
        for (int kc = 0; kc < 4; kc++) {
            #pragma unroll
            for (int dtp = 0; dtp < 4; dtp++) {
                uint32_t rh[4], rl[4];
                ldsm4t(rh, AV(buf,0, kc*16 + v_ro + lr, dtp*16 + v_co));
                ldsm4t(rl, AV(buf,1, kc*16 + v_ro + lr, dtp*16 + v_co));
                #pragma unroll
                for (int hv = 0; hv < 2; hv++) {
                    const int nt = 2*dtp + hv;
                    #pragma unroll
                    for (int mt = 0; mt < 2; mt++) {
                        mma16816(o[mt][nt], ah[mt][kc],  rh[2*hv], rh[2*hv+1]);
                        mma16816(o[mt][nt], ah[mt][kc],  rl[2*hv], rl[2*hv+1]);
                        mma16816(o[mt][nt], alo[mt][kc], rh[2*hv], rh[2*hv+1]);
                    }
                }
            }
        }
        __syncthreads();
    }

    // ---- normalize + split + store ----
    #pragma unroll
    for (int mt = 0; mt < 2; mt++) {
        const float inv0 = 1.f / ls[mt][0], inv1 = 1.f / ls[mt][1];
        const int grow = qbase + warp*32 + mt*16;
        #pragma unroll
        for (int nt = 0; nt < 8; nt++) {
            const int col = qoff + nt * 8 + 2 * t;
            size_t r0 = (size_t)(grow + g)     * N_EMBD + col;
            size_t r1 = (size_t)(grow + g + 8) * N_EMBD + col;
            uint32_t hh, ll;
            split2(o[mt][nt][0] * inv0, o[mt][nt][1] * inv0, hh, ll);
            *(uint32_t*)&yh[r0] = hh;
            *(uint32_t*)&yl[r0] = ll;
            split2(o[mt][nt][2] * inv1, o[mt][nt][3] * inv1, hh, ll);
            *(uint32_t*)&yh[r1] = hh;
            *(uint32_t*)&yl[r1] = ll;
        }
    }
}

// ---------------------------------------------------------------------------
extern "C" void kernel_launch(void* const* d_in, const int* in_sizes, int n_in,
                              void* d_out, int out_size)
{
    const float* x      = (const float*)d_in[0];
    const float* W_attn = (const float*)d_in[1];
    const float* b_attn = (const float*)d_in[2];
    const float* W_proj = (const float*)d_in[3];
    const float* b_proj = (const float*)d_in[4];
    float* out = (float*)d_out;

    bf16 *xh, *xl, *Wah, *Wal, *Wph, *Wpl, *qkvh, *qkvl, *yh, *yl;
    cudaGetSymbolAddress((void**)&xh,  g_xh);
    cudaGetSymbolAddress((void**)&xl,  g_xl);
    cudaGetSymbolAddress((void**)&Wah, g_Wah);
    cudaGetSymbolAddress((void**)&Wal, g_Wal);
    cudaGetSymbolAddress((void**)&Wph, g_Wph);
    cudaGetSymbolAddress((void**)&Wpl, g_Wpl);
    cudaGetSymbolAddress((void**)&qkvh, g_qkvh);
    cudaGetSymbolAddress((void**)&qkvl, g_qkvl);
    cudaGetSymbolAddress((void**)&yh,  g_yh);
    cudaGetSymbolAddress((void**)&yl,  g_yl);

    cudaFuncSetAttribute(gemm_mma<true>,
        cudaFuncAttributeMaxDynamicSharedMemorySize, G_SMEM);
    cudaFuncSetAttribute(gemm_mma<false>,
        cudaFuncAttributeMaxDynamicSharedMemorySize, G_SMEM);
    cudaFuncSetAttribute(attn_mma,
        cudaFuncAttributeMaxDynamicSharedMemorySize, ATTN_SMEM);

    // split inputs to bf16 hi/lo
    {
        int n4 = ROWS * N_EMBD / 4;
        split_kernel<<<(n4 + 255) / 256, 256>>>(x, xh, xl, n4);
        n4 = QKV_COLS * N_EMBD / 4;
        split_kernel<<<(n4 + 255) / 256, 256>>>(W_attn, Wah, Wal, n4);
        n4 = N_EMBD * N_EMBD / 4;
        split_kernel<<<(n4 + 255) / 256, 256>>>(W_proj, Wph, Wpl, n4);
    }

    // 1) qkv = x @ W_attn^T + b_attn  (epilogue splits to bf16 hi/lo)
    {
        dim3 grid(QKV_COLS / 128, ROWS / 128);
        gemm_mma<true><<<grid, 128, G_SMEM>>>(xh, xl, Wah, Wal, b_attn,
                                              nullptr, qkvh, qkvl,
                                              ROWS, QKV_COLS, N_EMBD);
    }

    // 2) flash attention
    {
        dim3 grid(SEQ / 128, N_HEAD, BATCH);
        attn_mma<<<grid, 128, ATTN_SMEM>>>(qkvh, qkvl, yh, yl);
    }

    // 3) out = y @ W_proj^T + b_proj  (fp32 output)
    {
        dim3 grid(N_EMBD / 128, ROWS / 128);
        gemm_mma<false><<<grid, 128, G_SMEM>>>(yh, yl, Wph, Wpl, b_proj,
                                               out, nullptr, nullptr,
                                               ROWS, N_EMBD, N_EMBD);
    }
}

// round 11
// speedup vs baseline: 5.4433x; 1.0004x over previous
#include <cuda_runtime.h>
#include <cuda_bf16.h>
#include <cstdint>

#define N_EMBD   768
#define N_HEAD   12
#define HEAD_DIM 64
#define BATCH    2
#define SEQ      4096
#define QKV_COLS 2304
#define ROWS     8192

typedef __nv_bfloat16 bf16;

// ---------------- scratch (device globals; no cudaMalloc allowed) ----------
__device__ bf16 g_xh [(size_t)ROWS * N_EMBD];
__device__ bf16 g_xl [(size_t)ROWS * N_EMBD];
__device__ bf16 g_Wah[(size_t)QKV_COLS * N_EMBD];
__device__ bf16 g_Wal[(size_t)QKV_COLS * N_EMBD];
__device__ bf16 g_Wph[(size_t)N_EMBD * N_EMBD];
__device__ bf16 g_Wpl[(size_t)N_EMBD * N_EMBD];
__device__ bf16 g_qkvh[(size_t)ROWS * QKV_COLS];
__device__ bf16 g_qkvl[(size_t)ROWS * QKV_COLS];
__device__ bf16 g_yh [(size_t)ROWS * N_EMBD];
__device__ bf16 g_yl [(size_t)ROWS * N_EMBD];

// ---------------- low-level helpers ----------------------------------------
__device__ __forceinline__ uint32_t smem_u32(const void* p) {
    return (uint32_t)__cvta_generic_to_shared(p);
}
__device__ __forceinline__ void cp16(const void* s, const void* g) {
    asm volatile("cp.async.cg.shared.global [%0], [%1], 16;"
                 :: "r"(smem_u32(s)), "l"(g));
}
__device__ __forceinline__ void cp_commit() {
    asm volatile("cp.async.commit_group;");
}
template<int N> __device__ __forceinline__ void cp_wait() {
    asm volatile("cp.async.wait_group %0;" :: "n"(N));
}
__device__ __forceinline__ void ldsm4(uint32_t* r, const void* p) {
    asm volatile("ldmatrix.sync.aligned.m8n8.x4.shared.b16 {%0,%1,%2,%3}, [%4];"
                 : "=r"(r[0]), "=r"(r[1]), "=r"(r[2]), "=r"(r[3])
                 : "r"(smem_u32(p)));
}
__device__ __forceinline__ void ldsm4t(uint32_t* r, const void* p) {
    asm volatile("ldmatrix.sync.aligned.m8n8.x4.trans.shared.b16 {%0,%1,%2,%3}, [%4];"
                 : "=r"(r[0]), "=r"(r[1]), "=r"(r[2]), "=r"(r[3])
                 : "r"(smem_u32(p)));
}
__device__ __forceinline__ void mma16816(float* c, const uint32_t* a,
                                         uint32_t b0, uint32_t b1)
{
    asm volatile(
        "mma.sync.aligned.m16n8k16.row.col.f32.bf16.bf16.f32 "
        "{%0,%1,%2,%3},{%4,%5,%6,%7},{%8,%9},{%0,%1,%2,%3};"
        : "+f"(c[0]), "+f"(c[1]), "+f"(c[2]), "+f"(c[3])
        : "r"(a[0]), "r"(a[1]), "r"(a[2]), "r"(a[3]), "r"(b0), "r"(b1));
}
__device__ __forceinline__ void split2(float v0, float v1,
                                       uint32_t& h, uint32_t& l)
{
    __nv_bfloat162 h2 = __floats2bfloat162_rn(v0, v1);
    float2 f = __bfloat1622float2(h2);
    __nv_bfloat162 l2 = __floats2bfloat162_rn(v0 - f.x, v1 - f.y);
    h = *reinterpret_cast<uint32_t*>(&h2);
    l = *reinterpret_cast<uint32_t*>(&l2);
}
__device__ __forceinline__ uint32_t bf2_mul(uint32_t a, uint32_t s)
{
    __nv_bfloat162 av = *reinterpret_cast<__nv_bfloat162*>(&a);
    __nv_bfloat162 sv = *reinterpret_cast<__nv_bfloat162*>(&s);
    __nv_bfloat162 r = __hmul2(av, sv);
    return *reinterpret_cast<uint32_t*>(&r);
}

// ---------------- fp32 -> (bf16 hi, bf16 lo) split -------------------------
__global__ void split_kernel(const float* __restrict__ in,
                             bf16* __restrict__ hi, bf16* __restrict__ lo,
                             int n4)
{
    int i = blockIdx.x * blockDim.x + threadIdx.x;
    if (i >= n4) return;
    float4 v = reinterpret_cast<const float4*>(in)[i];
    __nv_bfloat162 h0 = __floats2bfloat162_rn(v.x, v.y);
    __nv_bfloat162 h1 = __floats2bfloat162_rn(v.z, v.w);
    float2 f0 = __bfloat1622float2(h0);
    float2 f1 = __bfloat1622float2(h1);
    __nv_bfloat162 l0 = __floats2bfloat162_rn(v.x - f0.x, v.y - f0.y);
    __nv_bfloat162 l1 = __floats2bfloat162_rn(v.z - f1.x, v.w - f1.y);
    reinterpret_cast<__nv_bfloat162*>(hi)[2 * i]     = h0;
    reinterpret_cast<__nv_bfloat162*>(hi)[2 * i + 1] = h1;
    reinterpret_cast<__nv_bfloat162*>(lo)[2 * i]     = l0;
    reinterpret_cast<__nv_bfloat162*>(lo)[2 * i + 1] = l1;
}

// ---------------- split-bf16 GEMM: 128 thr, 2 CTAs/SM ----------------------
// C[M,N] = A[M,K] @ W[N,K]^T + bias;  Ah*Wh + Ah*Wl + Al*Wh.
// Term loops hoisted OUTSIDE tile loops: same-acc MMA reuse distance 8.
#define GA(buf,p,r,c) (smp         + (((buf)*2 + (p)) * 128 + (r)) * 40 + (c))
#define GB(buf,p,r,c) (smp + 20480 + (((buf)*2 + (p)) * 128 + (r)) * 40 + (c))
#define G_SMEM 81920

template<bool SPLIT_OUT>
__global__ __launch_bounds__(128, 2) void gemm_mma(
    const bf16* __restrict__ Ah, const bf16* __restrict__ Al,
    const bf16* __restrict__ Bh, const bf16* __restrict__ Bl,
    const float* __restrict__ bias,
    float* __restrict__ Cf, bf16* __restrict__ Ch, bf16* __restrict__ Cl,
    int M, int N, int K)
{
    extern __shared__ __align__(16) bf16 smp[];

    const int tid  = threadIdx.x;
    const int warp = tid >> 5;
    const int lane = tid & 31;
    const int g = lane >> 2;
    const int t = lane & 3;
    const int wm = (warp >> 1) * 64;
    const int wn = (warp & 1) * 64;
    const int bm = blockIdx.y * 128;
    const int bn = blockIdx.x * 128;

    const int lq = lane >> 3, lr = lane & 7;
    const int a_ro = (lq & 1) * 8, a_co = (lq >> 1) * 8;
    const int b_ro = (lq >> 1) * 8, b_co = (lq & 1) * 8;

    float acc[4][8][4] = {};
    const int iters = K / 32;

    auto load_tiles = [&](int s, int k0) {
        #pragma unroll
        for (int i = 0; i < 4; i++) {
            int idx = tid + i * 128;
            int r = idx >> 2, cc = (idx & 3) * 8;
            const size_t goa = (size_t)(bm + r) * K + k0 + cc;
            const size_t gob = (size_t)(bn + r) * K + k0 + cc;
            cp16(GA(s,0,r,cc), Ah + goa);
            cp16(GA(s,1,r,cc), Al + goa);
            cp16(GB(s,0,r,cc), Bh + gob);
            cp16(GB(s,1,r,cc), Bl + gob);
        }
        cp_commit();
    };

    load_tiles(0, 0);

    for (int it = 0; it < iters; it++) {
        if (it + 1 < iters) {
            load_tiles((it + 1) & 1, (it + 1) * 32);
            cp_wait<1>();
        } else {
            cp_wait<0>();
        }
        __syncthreads();

        const int buf = it & 1;
        #pragma unroll
        for (int kk = 0; kk < 32; kk += 16) {
            uint32_t a[2][4][4];
            #pragma unroll
            for (int mt = 0; mt < 4; mt++) {
                ldsm4(a[0][mt], GA(buf,0, wm + mt*16 + a_ro + lr, kk + a_co));
                ldsm4(a[1][mt], GA(buf,1, wm + mt*16 + a_ro + lr, kk + a_co));
            }
            #pragma unroll
            for (int ntp = 0; ntp < 4; ntp++) {
                uint32_t rh[4], rl[4];
                ldsm4(rh, GB(buf,0, wn + ntp*16 + b_ro + lr, kk + b_co));
                ldsm4(rl, GB(buf,1, wn + ntp*16 + b_ro + lr, kk + b_co));
                // term 1: Ah*Bh across all 8 accumulators (no RAW chain)
                #pragma unroll
                for (int hv = 0; hv < 2; hv++)
                    #pragma unroll
                    for (int mt = 0; mt < 4; mt++)
                        mma16816(acc[mt][2*ntp+hv], a[0][mt], rh[2*hv], rh[2*hv+1]);
                // term 2: Ah*Bl
                #pragma unroll
                for (int hv = 0; hv < 2; hv++)
                    #pragma unroll
                    for (int mt = 0; mt < 4; mt++)
                        mma16816(acc[mt][2*ntp+hv], a[0][mt], rl[2*hv], rl[2*hv+1]);
                // term 3: Al*Bh
                #pragma unroll
                for (int hv = 0; hv < 2; hv++)
                    #pragma unroll
                    for (int mt = 0; mt < 4; mt++)
                        mma16816(acc[mt][2*ntp+hv], a[1][mt], rh[2*hv], rh[2*hv+1]);
            }
        }
        __syncthreads();
    }

    // epilogue
    #pragma unroll
    for (int mt = 0; mt < 4; mt++) {
        #pragma unroll
        for (int nt = 0; nt < 8; nt++) {
            const int row = bm + wm + mt*16 + g;
            const int col = bn + wn + nt*8 + 2*t;
            float2 bs = *(const float2*)&bias[col];
            float v0 = acc[mt][nt][0] + bs.x;
            float v1 = acc[mt][nt][1] + bs.y;
            float v2 = acc[mt][nt][2] + bs.x;
            float v3 = acc[mt][nt][3] + bs.y;
            if (SPLIT_OUT) {
                uint32_t hh, ll;
                split2(v0, v1, hh, ll);
                *(uint32_t*)&Ch[(size_t)row * N + col] = hh;
                *(uint32_t*)&Cl[(size_t)row * N + col] = ll;
                split2(v2, v3, hh, ll);
                *(uint32_t*)&Ch[(size_t)(row + 8) * N + col] = hh;
                *(uint32_t*)&Cl[(size_t)(row + 8) * N + col] = ll;
            } else {
                *(float2*)&Cf[(size_t)row * N + col]       = make_float2(v0, v1);
                *(float2*)&Cf[(size_t)(row + 8) * N + col] = make_float2(v2, v3);
            }
        }
    }
}

// ---------------- flash attention: 128 thr, Q tile 128, 2 CTAs/SM ----------
#define SQ(p,r,c)     (smp +         ((p) * 128 + (r)) * 72 + (c))
#define AK(buf,p,r,c) (smp + 18432 + (((buf)*2 + (p)) * 64 + (r)) * 72 + (c))
#define AV(buf,p,r,c) (smp + 36864 + (((buf)*2 + (p)) * 64 + (r)) * 72 + (c))
#define ATTN_SMEM 110592

__global__ __launch_bounds__(128, 2) void attn_mma(
    const bf16* __restrict__ qh, const bf16* __restrict__ ql,
    bf16* __restrict__ yh, bf16* __restrict__ yl)
{
    extern __shared__ __align__(16) bf16 smp[];

    const int tid  = threadIdx.x;
    const int warp = tid >> 5;
    const int lane = tid & 31;
    const int g = lane >> 2;
    const int t = lane & 3;
    const int h = blockIdx.y;
    const int b = blockIdx.z;
    const int qoff = h * HEAD_DIM;
    const int qbase = b * SEQ + blockIdx.x * 128;

    const int lq = lane >> 3, lr = lane & 7;
    const int a_ro = (lq & 1) * 8, a_co = (lq >> 1) * 8;
    const int k_ro = (lq >> 1) * 8, k_co = (lq & 1) * 8;
    const int v_ro = (lq & 1) * 8,  v_co = (lq >> 1) * 8;

    // ---- fill Q smem (pre-scaled by 0.125, exact in bf16) ----
    {
        const uint32_t sc = 0x3E003E00u;
        const size_t base = (size_t)(qbase + tid) * QKV_COLS + qoff;
        #pragma unroll
        for (int c = 0; c < 64; c += 8) {
            uint4 vh = *(const uint4*)&qh[base + c];
            uint4 vl = *(const uint4*)&ql[base + c];
            uint32_t* ph = (uint32_t*)&vh;
            uint32_t* pl = (uint32_t*)&vl;
            #pragma unroll
            for (int j = 0; j < 4; j++) {
                ph[j] = bf2_mul(ph[j], sc);
                pl[j] = bf2_mul(pl[j], sc);
            }
            *(uint4*)SQ(0, tid, c) = vh;
            *(uint4*)SQ(1, tid, c) = vl;
        }
    }

    float o[2][8][4] = {};
    float mx[2][2] = {{-1e30f,-1e30f},{-1e30f,-1e30f}};
    float ls[2][2] = {};

    auto load_tile = [&](int kt, int buf) {
        #pragma unroll
        for (int i = 0; i < 2; i++) {
            int idx = tid + i * 128;
            int crow = idx >> 2, cseg = (idx & 3) * 16;
            const size_t base = (size_t)(b * SEQ + kt * 64 + crow) * QKV_COLS
                              + qoff + cseg;
            const bf16* skh = qh + base + N_EMBD;
            const bf16* skl = ql + base + N_EMBD;
            const bf16* svh = qh + base + 2 * N_EMBD;
            const bf16* svl = ql + base + 2 * N_EMBD;
            cp16(AK(buf,0,crow,cseg), skh);  cp16(AK(buf,0,crow,cseg+8), skh+8);
            cp16(AK(buf,1,crow,cseg), skl);  cp16(AK(buf,1,crow,cseg+8), skl+8);
            cp16(AV(buf,0,crow,cseg), svh);  cp16(AV(buf,0,crow,cseg+8), svh+8);
            cp16(AV(buf,1,crow,cseg), svl);  cp16(AV(buf,1,crow,cseg+8), svl+8);
        }
        cp_commit();
    };

    load_tile(0, 0);

    const int NT = SEQ / 64;
    for (int kt = 0; kt < NT; kt++) {
        if (kt + 1 < NT) { load_tile(kt + 1, (kt + 1) & 1); cp_wait<1>(); }
        else             { cp_wait<0>(); }
        __syncthreads();
        const int buf = kt & 1;

        // ---- S = Qs @ K^T (32 rows/warp); terms separated ----
        float s[2][8][4] = {};
        #pragma unroll
        for (int kk = 0; kk < 4; kk++) {
            uint32_t qa[2][2][4];
            #pragma unroll
            for (int mt = 0; mt < 2; mt++) {
                ldsm4(qa[0][mt], SQ(0, warp*32 + mt*16 + a_ro + lr, kk*16 + a_co));
                ldsm4(qa[1][mt], SQ(1, warp*32 + mt*16 + a_ro + lr, kk*16 + a_co));
            }
            #pragma unroll
            for (int ntp = 0; ntp < 4; ntp++) {
                uint32_t rh[4], rl[4];
                ldsm4(rh, AK(buf,0, ntp*16 + k_ro + lr, kk*16 + k_co));
                ldsm4(rl, AK(buf,1, ntp*16 + k_ro + lr, kk*16 + k_co));
                #pragma unroll
                for (int hv = 0; hv < 2; hv++)
                    #pragma unroll
                    for (int mt = 0; mt < 2; mt++)
                        mma16816(s[mt][2*ntp+hv], qa[0][mt], rh[2*hv], rh[2*hv+1]);
                #pragma unroll
                for (int hv = 0; hv < 2; hv++)
                    #pragma unroll
                    for (int mt = 0; mt < 2; mt++)
                        mma16816(s[mt][2*ntp+hv], qa[0][mt], rl[2*hv], rl[2*hv+1]);
                #pragma unroll
                for (int hv = 0; hv < 2; hv++)
                    #pragma unroll
                    for (int mt = 0; mt < 2; mt++)
                        mma16816(s[mt][2*ntp+hv], qa[1][mt], rh[2*hv], rh[2*hv+1]);
            }
        }

        // ---- online softmax + P split ----
        uint32_t ah[2][4][4], alo[2][4][4];
        #pragma unroll
        for (int mt = 0; mt < 2; mt++) {
            float r0 = -1e30f, r1 = -1e30f;
            #pragma unroll
            for (int nt = 0; nt < 8; nt++) {
                r0 = fmaxf(r0, fmaxf(s[mt][nt][0], s[mt][nt][1]));
                r1 = fmaxf(r1, fmaxf(s[mt][nt][2], s[mt][nt][3]));
            }
            r0 = fmaxf(r0, __shfl_xor_sync(0xffffffffu, r0, 1));
            r0 = fmaxf(r0, __shfl_xor_sync(0xffffffffu, r0, 2));
            r1 = fmaxf(r1, __shfl_xor_sync(0xffffffffu, r1, 1));
            r1 = fmaxf(r1, __shfl_xor_sync(0xffffffffu, r1, 2));

            const float mn0 = fmaxf(mx[mt][0], r0);
            const float mn1 = fmaxf(mx[mt][1], r1);
            const float a0 = __expf(mx[mt][0] - mn0);
            const float a1 = __expf(mx[mt][1] - mn1);
            mx[mt][0] = mn0; mx[mt][1] = mn1;
            #pragma unroll
            for (int nt = 0; nt < 8; nt++) {
                o[mt][nt][0] *= a0; o[mt][nt][1] *= a0;
                o[mt][nt][2] *= a1; o[mt][nt][3] *= a1;
            }
            float t0 = 0.f, t1 = 0.f;
            #pragma unroll
            for (int nt = 0; nt < 8; nt++) {
                const float p0 = __expf(s[mt][nt][0] - mn0);
                const float p1 = __expf(s[mt][nt][1] - mn0);
                const float p2 = __expf(s[mt][nt][2] - mn1);
                const float p3 = __expf(s[mt][nt][3] - mn1);
                t0 += p0 + p1;
                t1 += p2 + p3;
                const int kc = nt >> 1, hf = nt & 1;
                split2(p0, p1, ah[mt][kc][hf ? 2 : 0], alo[mt][kc][hf ? 2 : 0]);
                split2(p2, p3, ah[mt][kc][hf ? 3 : 1], alo[mt][kc][hf ? 3 : 1]);
            }
            t0 += __shfl_xor_sync(0xffffffffu, t0, 1);
            t0 += __shfl_xor_sync(0xffffffffu, t0, 2);
            t1 += __shfl_xor_sync(0xffffffffu, t1, 1);
            t1 += __shfl_xor_sync(0xffffffffu, t1, 2);
            ls[mt][0] = ls[mt][0] * a0 + t0;
            ls[mt][1] = ls[mt][1] * a1 + t1;
        }

        // ---- O += P @ V; terms separated ----
        #pragma unroll
        for (int kc = 0; kc < 4; kc++) {
            #pragma unroll
            for (int dtp = 0; dtp < 4; dtp++) {
                uint32_t rh[4], rl[4];
                ldsm4t(rh, AV(buf,0, kc*16 + v_ro + lr, dtp*16 + v_co));
                ldsm4t(rl, AV(buf,1, kc*16 + v_ro + lr, dtp*16 + v_co));
                #pragma unroll
                for (int hv = 0; hv < 2; hv++)
                    #pragma unroll
                    for (int mt = 0; mt < 2; mt++)
                        mma16816(o[mt][2*dtp+hv], ah[mt][kc], rh[2*hv], rh[2*hv+1]);
                #pragma unroll
                for (int hv = 0; hv < 2; hv++)
                    #pragma unroll
                    for (int mt = 0; mt < 2; mt++)
                        mma16816(o[mt][2*dtp+hv], ah[mt][kc], rl[2*hv], rl[2*hv+1]);
                #pragma unroll
                for (int hv = 0; hv < 2; hv++)
                    #pragma unroll
                    for (int mt = 0; mt < 2; mt++)
                        mma16816(o[mt][2*dtp+hv], alo[mt][kc], rh[2*hv], rh[2*hv+1]);
            }
        }
        __syncthreads();
    }

    // ---- normalize + split + store ----
    #pragma unroll
    for (int mt = 0; mt < 2; mt++) {
        const float inv0 = 1.f / ls[mt][0], inv1 = 1.f / ls[mt][1];
        const int grow = qbase + warp*32 + mt*16;
        #pragma unroll
        for (int nt = 0; nt < 8; nt++) {
            const int col = qoff + nt * 8 + 2 * t;
            size_t r0 = (size_t)(grow + g)     * N_EMBD + col;
            size_t r1 = (size_t)(grow + g + 8) * N_EMBD + col;
            uint32_t hh, ll;
            split2(o[mt][nt][0] * inv0, o[mt][nt][1] * inv0, hh, ll);
            *(uint32_t*)&yh[r0] = hh;
            *(uint32_t*)&yl[r0] = ll;
            split2(o[mt][nt][2] * inv1, o[mt][nt][3] * inv1, hh, ll);
            *(uint32_t*)&yh[r1] = hh;
            *(uint32_t*)&yl[r1] = ll;
        }
    }
}

// ---------------------------------------------------------------------------
extern "C" void kernel_launch(void* const* d_in, const int* in_sizes, int n_in,
                              void* d_out, int out_size)
{
    const float* x      = (const float*)d_in[0];
    const float* W_attn = (const float*)d_in[1];
    const float* b_attn = (const float*)d_in[2];
    const float* W_proj = (const float*)d_in[3];
    const float* b_proj = (const float*)d_in[4];
    float* out = (float*)d_out;

    bf16 *xh, *xl, *Wah, *Wal, *Wph, *Wpl, *qkvh, *qkvl, *yh, *yl;
    cudaGetSymbolAddress((void**)&xh,  g_xh);
    cudaGetSymbolAddress((void**)&xl,  g_xl);
    cudaGetSymbolAddress((void**)&Wah, g_Wah);
    cudaGetSymbolAddress((void**)&Wal, g_Wal);
    cudaGetSymbolAddress((void**)&Wph, g_Wph);
    cudaGetSymbolAddress((void**)&Wpl, g_Wpl);
    cudaGetSymbolAddress((void**)&qkvh, g_qkvh);
    cudaGetSymbolAddress((void**)&qkvl, g_qkvl);
    cudaGetSymbolAddress((void**)&yh,  g_yh);
    cudaGetSymbolAddress((void**)&yl,  g_yl);

    cudaFuncSetAttribute(gemm_mma<true>,
        cudaFuncAttributeMaxDynamicSharedMemorySize, G_SMEM);
    cudaFuncSetAttribute(gemm_mma<false>,
        cudaFuncAttributeMaxDynamicSharedMemorySize, G_SMEM);
    cudaFuncSetAttribute(attn_mma,
        cudaFuncAttributeMaxDynamicSharedMemorySize, ATTN_SMEM);

    // split inputs to bf16 hi/lo
    {
        int n4 = ROWS * N_EMBD / 4;
        split_kernel<<<(n4 + 255) / 256, 256>>>(x, xh, xl, n4);
        n4 = QKV_COLS * N_EMBD / 4;
        split_kernel<<<(n4 + 255) / 256, 256>>>(W_attn, Wah, Wal, n4);
        n4 = N_EMBD * N_EMBD / 4;
        split_kernel<<<(n4 + 255) / 256, 256>>>(W_proj, Wph, Wpl, n4);
    }

    // 1) qkv = x @ W_attn^T + b_attn  (epilogue splits to bf16 hi/lo)
    {
        dim3 grid(QKV_COLS / 128, ROWS / 128);
        gemm_mma<true><<<grid, 128, G_SMEM>>>(xh, xl, Wah, Wal, b_attn,
                                              nullptr, qkvh, qkvl,
                                              ROWS, QKV_COLS, N_EMBD);
    }

    // 2) flash attention
    {
        dim3 grid(SEQ / 128, N_HEAD, BATCH);
        attn_mma<<<grid, 128, ATTN_SMEM>>>(qkvh, qkvl, yh, yl);
    }

    // 3) out = y @ W_proj^T + b_proj  (fp32 output)
    {
        dim3 grid(N_EMBD / 128, ROWS / 128);
        gemm_mma<false><<<grid, 128, G_SMEM>>>(yh, yl, Wph, Wpl, b_proj,
                                               out, nullptr, nullptr,
                                               ROWS, N_EMBD, N_EMBD);
    }
}

// round 12
// speedup vs baseline: 7.5748x; 1.3916x over previous
#include <cuda_runtime.h>
#include <cuda_fp16.h>
#include <cstdint>

#define N_EMBD   768
#define N_HEAD   12
#define HEAD_DIM 64
#define BATCH    2
#define SEQ      4096
#define QKV_COLS 2304
#define ROWS     8192

typedef __half fp16;

// ---------------- scratch (device globals; no cudaMalloc allowed) ----------
__device__ fp16 g_xh [(size_t)ROWS * N_EMBD];
__device__ fp16 g_xl [(size_t)ROWS * N_EMBD];
__device__ fp16 g_Wah[(size_t)QKV_COLS * N_EMBD];   // hi only used
__device__ fp16 g_Wal[(size_t)QKV_COLS * N_EMBD];
__device__ fp16 g_Wph[(size_t)N_EMBD * N_EMBD];     // hi only used
__device__ fp16 g_Wpl[(size_t)N_EMBD * N_EMBD];
__device__ fp16 g_qkvh[(size_t)ROWS * QKV_COLS];
__device__ fp16 g_qkvl[(size_t)ROWS * QKV_COLS];    // only q-lo read
__device__ fp16 g_yh [(size_t)ROWS * N_EMBD];
__device__ fp16 g_yl [(size_t)ROWS * N_EMBD];

// ---------------- low-level helpers ----------------------------------------
__device__ __forceinline__ uint32_t smem_u32(const void* p) {
    return (uint32_t)__cvta_generic_to_shared(p);
}
__device__ __forceinline__ void cp16(const void* s, const void* g) {
    asm volatile("cp.async.cg.shared.global [%0], [%1], 16;"
                 :: "r"(smem_u32(s)), "l"(g));
}
__device__ __forceinline__ void cp_commit() {
    asm volatile("cp.async.commit_group;");
}
template<int N> __device__ __forceinline__ void cp_wait() {
    asm volatile("cp.async.wait_group %0;" :: "n"(N));
}
__device__ __forceinline__ void ldsm4(uint32_t* r, const void* p) {
    asm volatile("ldmatrix.sync.aligned.m8n8.x4.shared.b16 {%0,%1,%2,%3}, [%4];"
                 : "=r"(r[0]), "=r"(r[1]), "=r"(r[2]), "=r"(r[3])
                 : "r"(smem_u32(p)));
}
__device__ __forceinline__ void ldsm4t(uint32_t* r, const void* p) {
    asm volatile("ldmatrix.sync.aligned.m8n8.x4.trans.shared.b16 {%0,%1,%2,%3}, [%4];"
                 : "=r"(r[0]), "=r"(r[1]), "=r"(r[2]), "=r"(r[3])
                 : "r"(smem_u32(p)));
}
__device__ __forceinline__ void mma16816(float* c, const uint32_t* a,
                                         uint32_t b0, uint32_t b1)
{
    asm volatile(
        "mma.sync.aligned.m16n8k16.row.col.f32.f16.f16.f32 "
        "{%0,%1,%2,%3},{%4,%5,%6,%7},{%8,%9},{%0,%1,%2,%3};"
        : "+f"(c[0]), "+f"(c[1]), "+f"(c[2]), "+f"(c[3])
        : "r"(a[0]), "r"(a[1]), "r"(a[2]), "r"(a[3]), "r"(b0), "r"(b1));
}
__device__ __forceinline__ void split2(float v0, float v1,
                                       uint32_t& h, uint32_t& l)
{
    __half2 h2 = __floats2half2_rn(v0, v1);
    float2 f = __half22float2(h2);
    __half2 l2 = __floats2half2_rn(v0 - f.x, v1 - f.y);
    h = *reinterpret_cast<uint32_t*>(&h2);
    l = *reinterpret_cast<uint32_t*>(&l2);
}
__device__ __forceinline__ uint32_t h2_mul(uint32_t a, uint32_t s)
{
    __half2 av = *reinterpret_cast<__half2*>(&a);
    __half2 sv = *reinterpret_cast<__half2*>(&s);
    __half2 r = __hmul2(av, sv);
    return *reinterpret_cast<uint32_t*>(&r);
}

// ---------------- fp32 -> (fp16 hi, fp16 lo) split -------------------------
__global__ void split_kernel(const float* __restrict__ in,
                             fp16* __restrict__ hi, fp16* __restrict__ lo,
                             int n4)
{
    int i = blockIdx.x * blockDim.x + threadIdx.x;
    if (i >= n4) return;
    float4 v = reinterpret_cast<const float4*>(in)[i];
    __half2 h0 = __floats2half2_rn(v.x, v.y);
    __half2 h1 = __floats2half2_rn(v.z, v.w);
    float2 f0 = __half22float2(h0);
    float2 f1 = __half22float2(h1);
    __half2 l0 = __floats2half2_rn(v.x - f0.x, v.y - f0.y);
    __half2 l1 = __floats2half2_rn(v.z - f1.x, v.w - f1.y);
    reinterpret_cast<__half2*>(hi)[2 * i]     = h0;
    reinterpret_cast<__half2*>(hi)[2 * i + 1] = h1;
    reinterpret_cast<__half2*>(lo)[2 * i]     = l0;
    reinterpret_cast<__half2*>(lo)[2 * i + 1] = l1;
}

// ---------------- 2-term fp16 GEMM: 128 thr, 2 CTAs/SM ---------------------
// C[M,N] = A[M,K] @ W[N,K]^T + bias;  C = Ah*Bh + Al*Bh  (B rounded to fp16)
// 128 threads (4 warps 2m x 2n), BM=128, BN=128, BK=32; warp tile 64x64.
// dyn smem: A hi/lo double-buffered + B hi double-buffered = 61440 B.
#define GA(buf,p,r,c) (smp         + (((buf)*2 + (p)) * 128 + (r)) * 40 + (c))
#define GB(buf,r,c)   (smp + 20480 + (((buf))         * 128 + (r)) * 40 + (c))
#define G_SMEM 61440

template<bool SPLIT_OUT>
__global__ __launch_bounds__(128, 2) void gemm_mma(
    const fp16* __restrict__ Ah, const fp16* __restrict__ Al,
    const fp16* __restrict__ Bh,
    const float* __restrict__ bias,
    float* __restrict__ Cf, fp16* __restrict__ Ch, fp16* __restrict__ Cl,
    int M, int N, int K)
{
    extern __shared__ __align__(16) fp16 smp[];

    const int tid  = threadIdx.x;
    const int warp = tid >> 5;
    const int lane = tid & 31;
    const int g = lane >> 2;
    const int t = lane & 3;
    const int wm = (warp >> 1) * 64;
    const int wn = (warp & 1) * 64;
    const int bm = blockIdx.y * 128;
    const int bn = blockIdx.x * 128;

    const int lq = lane >> 3, lr = lane & 7;
    const int a_ro = (lq & 1) * 8, a_co = (lq >> 1) * 8;
    const int b_ro = (lq >> 1) * 8, b_co = (lq & 1) * 8;

    float acc[4][8][4] = {};
    const int iters = K / 32;

    auto load_tiles = [&](int s, int k0) {
        #pragma unroll
        for (int i = 0; i < 4; i++) {
            int idx = tid + i * 128;
            int r = idx >> 2, cc = (idx & 3) * 8;
            const size_t goa = (size_t)(bm + r) * K + k0 + cc;
            const size_t gob = (size_t)(bn + r) * K + k0 + cc;
            cp16(GA(s,0,r,cc), Ah + goa);
            cp16(GA(s,1,r,cc), Al + goa);
            cp16(GB(s,r,cc),   Bh + gob);
        }
        cp_commit();
    };

    load_tiles(0, 0);

    for (int it = 0; it < iters; it++) {
        if (it + 1 < iters) {
            load_tiles((it + 1) & 1, (it + 1) * 32);
            cp_wait<1>();
        } else {
            cp_wait<0>();
        }
        __syncthreads();

        const int buf = it & 1;
        #pragma unroll
        for (int kk = 0; kk < 32; kk += 16) {
            uint32_t a[2][4][4];
            #pragma unroll
            for (int mt = 0; mt < 4; mt++) {
                ldsm4(a[0][mt], GA(buf,0, wm + mt*16 + a_ro + lr, kk + a_co));
                ldsm4(a[1][mt], GA(buf,1, wm + mt*16 + a_ro + lr, kk + a_co));
            }
            #pragma unroll
            for (int ntp = 0; ntp < 4; ntp++) {
                uint32_t rh[4];
                ldsm4(rh, GB(buf, wn + ntp*16 + b_ro + lr, kk + b_co));
                #pragma unroll
                for (int hv = 0; hv < 2; hv++) {
                    const uint32_t b0 = rh[2*hv], b1 = rh[2*hv+1];
                    #pragma unroll
                    for (int mt = 0; mt < 4; mt++) {
                        mma16816(acc[mt][2*ntp+hv], a[0][mt], b0, b1);
                        mma16816(acc[mt][2*ntp+hv], a[1][mt], b0, b1);
                    }
                }
            }
        }
        __syncthreads();
    }

    // epilogue
    #pragma unroll
    for (int mt = 0; mt < 4; mt++) {
        #pragma unroll
        for (int nt = 0; nt < 8; nt++) {
            const int row = bm + wm + mt*16 + g;
            const int col = bn + wn + nt*8 + 2*t;
            float2 bs = *(const float2*)&bias[col];
            float v0 = acc[mt][nt][0] + bs.x;
            float v1 = acc[mt][nt][1] + bs.y;
            float v2 = acc[mt][nt][2] + bs.x;
            float v3 = acc[mt][nt][3] + bs.y;
            if (SPLIT_OUT) {
                uint32_t hh, ll;
                split2(v0, v1, hh, ll);
                *(uint32_t*)&Ch[(size_t)row * N + col] = hh;
                *(uint32_t*)&Cl[(size_t)row * N + col] = ll;
                split2(v2, v3, hh, ll);
                *(uint32_t*)&Ch[(size_t)(row + 8) * N + col] = hh;
                *(uint32_t*)&Cl[(size_t)(row + 8) * N + col] = ll;
            } else {
                *(float2*)&Cf[(size_t)row * N + col]       = make_float2(v0, v1);
                *(float2*)&Cf[(size_t)(row + 8) * N + col] = make_float2(v2, v3);
            }
        }
    }
}

// ---------------- flash attention: 2-term fp16, Q tile 128, 2 CTAs/SM ------
// Q split (hi+lo) in smem; K, V rounded (hi only), double-buffered.
// smem elems: Q[2][128][72] (18432) | K[2][64][72] (9216) | V[2][64][72]
#define SQ(p,r,c)   (smp +         ((p)   * 128 + (r)) * 72 + (c))
#define AK(buf,r,c) (smp + 18432 + ((buf) * 64  + (r)) * 72 + (c))
#define AV(buf,r,c) (smp + 27648 + ((buf) * 64  + (r)) * 72 + (c))
#define ATTN_SMEM 73728

__global__ __launch_bounds__(128, 2) void attn_mma(
    const fp16* __restrict__ qh, const fp16* __restrict__ ql,
    fp16* __restrict__ yh, fp16* __restrict__ yl)
{
    extern __shared__ __align__(16) fp16 smp[];

    const int tid  = threadIdx.x;
    const int warp = tid >> 5;
    const int lane = tid & 31;
    const int g = lane >> 2;
    const int t = lane & 3;
    const int h = blockIdx.y;
    const int b = blockIdx.z;
    const int qoff = h * HEAD_DIM;
    const int qbase = b * SEQ + blockIdx.x * 128;

    const int lq = lane >> 3, lr = lane & 7;
    const int a_ro = (lq & 1) * 8, a_co = (lq >> 1) * 8;
    const int k_ro = (lq >> 1) * 8, k_co = (lq & 1) * 8;
    const int v_ro = (lq & 1) * 8,  v_co = (lq >> 1) * 8;

    // ---- fill Q smem (pre-scaled by 0.125, exact in fp16) ----
    {
        const uint32_t sc = 0x30003000u;   // half2 {0.125, 0.125}
        const size_t base = (size_t)(qbase + tid) * QKV_COLS + qoff;
        #pragma unroll
        for (int c = 0; c < 64; c += 8) {
            uint4 vh = *(const uint4*)&qh[base + c];
            uint4 vl = *(const uint4*)&ql[base + c];
            uint32_t* ph = (uint32_t*)&vh;
            uint32_t* pl = (uint32_t*)&vl;
            #pragma unroll
            for (int j = 0; j < 4; j++) {
                ph[j] = h2_mul(ph[j], sc);
                pl[j] = h2_mul(pl[j], sc);
            }
            *(uint4*)SQ(0, tid, c) = vh;
            *(uint4*)SQ(1, tid, c) = vl;
        }
    }

    float o[2][8][4] = {};
    float mx[2][2] = {{-1e30f,-1e30f},{-1e30f,-1e30f}};
    float ls[2][2] = {};

    auto load_tile = [&](int kt, int buf) {
        #pragma unroll
        for (int i = 0; i < 2; i++) {
            int idx = tid + i * 128;
            int crow = idx >> 2, cseg = (idx & 3) * 16;
            const size_t base = (size_t)(b * SEQ + kt * 64 + crow) * QKV_COLS
                              + qoff + cseg;
            const fp16* skh = qh + base + N_EMBD;          // K hi
            const fp16* svh = qh + base + 2 * N_EMBD;      // V hi
            cp16(AK(buf,crow,cseg), skh);  cp16(AK(buf,crow,cseg+8), skh+8);
            cp16(AV(buf,crow,cseg), svh);  cp16(AV(buf,crow,cseg+8), svh+8);
        }
        cp_commit();
    };

    load_tile(0, 0);

    const int NT = SEQ / 64;
    for (int kt = 0; kt < NT; kt++) {
        if (kt + 1 < NT) { load_tile(kt + 1, (kt + 1) & 1); cp_wait<1>(); }
        else             { cp_wait<0>(); }
        __syncthreads();
        const int buf = kt & 1;

        // ---- S = Qs @ K^T : Qh*Kh + Ql*Kh ----
        float s[2][8][4] = {};
        #pragma unroll
        for (int kk = 0; kk < 4; kk++) {
            uint32_t qa[2][2][4];
            #pragma unroll
            for (int mt = 0; mt < 2; mt++) {
                ldsm4(qa[0][mt], SQ(0, warp*32 + mt*16 + a_ro + lr, kk*16 + a_co));
                ldsm4(qa[1][mt], SQ(1, warp*32 + mt*16 + a_ro + lr, kk*16 + a_co));
            }
            #pragma unroll
            for (int ntp = 0; ntp < 4; ntp++) {
                uint32_t rh[4];
                ldsm4(rh, AK(buf, ntp*16 + k_ro + lr, kk*16 + k_co));
                #pragma unroll
                for (int hv = 0; hv < 2; hv++) {
                    const uint32_t b0 = rh[2*hv], b1 = rh[2*hv+1];
                    #pragma unroll
                    for (int mt = 0; mt < 2; mt++) {
                        mma16816(s[mt][2*ntp+hv], qa[0][mt], b0, b1);
                        mma16816(s[mt][2*ntp+hv], qa[1][mt], b0, b1);
                    }
                }
            }
        }

        // ---- online softmax + P split ----
        uint32_t ah[2][4][4], alo[2][4][4];
        #pragma unroll
        for (int mt = 0; mt < 2; mt++) {
            float r0 = -1e30f, r1 = -1e30f;
            #pragma unroll
            for (int nt = 0; nt < 8; nt++) {
                r0 = fmaxf(r0, fmaxf(s[mt][nt][0], s[mt][nt][1]));
                r1 = fmaxf(r1, fmaxf(s[mt][nt][2], s[mt][nt][3]));
            }
            r0 = fmaxf(r0, __shfl_xor_sync(0xffffffffu, r0, 1));
            r0 = fmaxf(r0, __shfl_xor_sync(0xffffffffu, r0, 2));
            r1 = fmaxf(r1, __shfl_xor_sync(0xffffffffu, r1, 1));
            r1 = fmaxf(r1, __shfl_xor_sync(0xffffffffu, r1, 2));

            const float mn0 = fmaxf(mx[mt][0], r0);
            const float mn1 = fmaxf(mx[mt][1], r1);
            const float a0 = __expf(mx[mt][0] - mn0);
            const float a1 = __expf(mx[mt][1] - mn1);
            mx[mt][0] = mn0; mx[mt][1] = mn1;
            #pragma unroll
            for (int nt = 0; nt < 8; nt++) {
                o[mt][nt][0] *= a0; o[mt][nt][1] *= a0;
                o[mt][nt][2] *= a1; o[mt][nt][3] *= a1;
            }
            float t0 = 0.f, t1 = 0.f;
            #pragma unroll
            for (int nt = 0; nt < 8; nt++) {
                const float p0 = __expf(s[mt][nt][0] - mn0);
                const float p1 = __expf(s[mt][nt][1] - mn0);
                const float p2 = __expf(s[mt][nt][2] - mn1);
                const float p3 = __expf(s[mt][nt][3] - mn1);
                t0 += p0 + p1;
                t1 += p2 + p3;
                const int kc = nt >> 1, hf = nt & 1;
                split2(p0, p1, ah[mt][kc][hf ? 2 : 0], alo[mt][kc][hf ? 2 : 0]);
                split2(p2, p3, ah[mt][kc][hf ? 3 : 1], alo[mt][kc][hf ? 3 : 1]);
            }
            t0 += __shfl_xor_sync(0xffffffffu, t0, 1);
            t0 += __shfl_xor_sync(0xffffffffu, t0, 2);
            t1 += __shfl_xor_sync(0xffffffffu, t1, 1);
            t1 += __shfl_xor_sync(0xffffffffu, t1, 2);
            ls[mt][0] = ls[mt][0] * a0 + t0;
            ls[mt][1] = ls[mt][1] * a1 + t1;
        }

        // ---- O += P @ V : Ph*Vh + Pl*Vh ----
        #pragma unroll
        for (int kc = 0; kc < 4; kc++) {
            #pragma unroll
            for (int dtp = 0; dtp < 4; dtp++) {
                uint32_t rh[4];
                ldsm4t(rh, AV(buf, kc*16 + v_ro + lr, dtp*16 + v_co));
                #pragma unroll
                for (int hv = 0; hv < 2; hv++) {
                    const uint32_t b0 = rh[2*hv], b1 = rh[2*hv+1];
                    #pragma unroll
                    for (int mt = 0; mt < 2; mt++) {
                        mma16816(o[mt][2*dtp+hv], ah[mt][kc],  b0, b1);
                        mma16816(o[mt][2*dtp+hv], alo[mt][kc], b0, b1);
                    }
                }
            }
        }
        __syncthreads();
    }

    // ---- normalize + split + store ----
    #pragma unroll
    for (int mt = 0; mt < 2; mt++) {
        const float inv0 = 1.f / ls[mt][0], inv1 = 1.f / ls[mt][1];
        const int grow = qbase + warp*32 + mt*16;
        #pragma unroll
        for (int nt = 0; nt < 8; nt++) {
            const int col = qoff + nt * 8 + 2 * t;
            size_t r0 = (size_t)(grow + g)     * N_EMBD + col;
            size_t r1 = (size_t)(grow + g + 8) * N_EMBD + col;
            uint32_t hh, ll;
            split2(o[mt][nt][0] * inv0, o[mt][nt][1] * inv0, hh, ll);
            *(uint32_t*)&yh[r0] = hh;
            *(uint32_t*)&yl[r0] = ll;
            split2(o[mt][nt][2] * inv1, o[mt][nt][3] * inv1, hh, ll);
            *(uint32_t*)&yh[r1] = hh;
            *(uint32_t*)&yl[r1] = ll;
        }
    }
}

// ---------------------------------------------------------------------------
extern "C" void kernel_launch(void* const* d_in, const int* in_sizes, int n_in,
                              void* d_out, int out_size)
{
    const float* x      = (const float*)d_in[0];
    const float* W_attn = (const float*)d_in[1];
    const float* b_attn = (const float*)d_in[2];
    const float* W_proj = (const float*)d_in[3];
    const float* b_proj = (const float*)d_in[4];
    float* out = (float*)d_out;

    fp16 *xh, *xl, *Wah, *Wal, *Wph, *Wpl, *qkvh, *qkvl, *yh, *yl;
    cudaGetSymbolAddress((void**)&xh,  g_xh);
    cudaGetSymbolAddress((void**)&xl,  g_xl);
    cudaGetSymbolAddress((void**)&Wah, g_Wah);
    cudaGetSymbolAddress((void**)&Wal, g_Wal);
    cudaGetSymbolAddress((void**)&Wph, g_Wph);
    cudaGetSymbolAddress((void**)&Wpl, g_Wpl);
    cudaGetSymbolAddress((void**)&qkvh, g_qkvh);
    cudaGetSymbolAddress((void**)&qkvl, g_qkvl);
    cudaGetSymbolAddress((void**)&yh,  g_yh);
    cudaGetSymbolAddress((void**)&yl,  g_yl);

    cudaFuncSetAttribute(gemm_mma<true>,
        cudaFuncAttributeMaxDynamicSharedMemorySize, G_SMEM);
    cudaFuncSetAttribute(gemm_mma<false>,
        cudaFuncAttributeMaxDynamicSharedMemorySize, G_SMEM);
    cudaFuncSetAttribute(attn_mma,
        cudaFuncAttributeMaxDynamicSharedMemorySize, ATTN_SMEM);

    // split inputs to fp16 hi/lo (lo of weights is written but unused)
    {
        int n4 = ROWS * N_EMBD / 4;
        split_kernel<<<(n4 + 255) / 256, 256>>>(x, xh, xl, n4);
        n4 = QKV_COLS * N_EMBD / 4;
        split_kernel<<<(n4 + 255) / 256, 256>>>(W_attn, Wah, Wal, n4);
        n4 = N_EMBD * N_EMBD / 4;
        split_kernel<<<(n4 + 255) / 256, 256>>>(W_proj, Wph, Wpl, n4);
    }

    // 1) qkv = x @ W_attn^T + b_attn  (epilogue splits to fp16 hi/lo)
    {
        dim3 grid(QKV_COLS / 128, ROWS / 128);
        gemm_mma<true><<<grid, 128, G_SMEM>>>(xh, xl, Wah, b_attn,
                                              nullptr, qkvh, qkvl,
                                              ROWS, QKV_COLS, N_EMBD);
    }

    // 2) flash attention
    {
        dim3 grid(SEQ / 128, N_HEAD, BATCH);
        attn_mma<<<grid, 128, ATTN_SMEM>>>(qkvh, qkvl, yh, yl);
    }

    // 3) out = y @ W_proj^T + b_proj  (fp32 output)
    {
        dim3 grid(N_EMBD / 128, ROWS / 128);
        gemm_mma<false><<<grid, 128, G_SMEM>>>(yh, yl, Wph, b_proj,
                                               out, nullptr, nullptr,
                                               ROWS, N_EMBD, N_EMBD);
    }
}